// round 11
// baseline (speedup 1.0000x reference)
#include <cuda_runtime.h>
#include <math.h>

// ---------------- problem dims ----------------
#define NN 1000
#define TT 4000
#define BB 16
#define SS 12
#define HH 12
#define C1C 8
#define C2C 16
#define KW 10
#define DD 128
#define HID 64
#define INF 65           // 1 + HID
#define T1L (TT-KW+1)    // 3991
#define T2L (T1L-KW+1)   // 3982
#define BFCOLS (BB*INF)  // 1040

// padded GEMM dims (zero-pad regions are never written -> stay 0 from static init)
#define MP 1024
#define KP 1024
#define NPS 1088         // padded column stride (17 * 64)

// ---------------- scratch (device globals; no allocation allowed) ----------------
__device__ __align__(16) float g_A[MP*KP];
__device__ __align__(16) float g_cat[KP*NPS];
__device__ __align__(16) float g_cat2[KP*NPS];
__device__ __align__(16) float g_agg[MP*NPS];
__device__ __align__(16) float g_agg2[MP*NPS];
__device__ __align__(16) float g_h[BB*NN*HID];     // layout: rid = n*16+b, [rid][HID]
__device__ __align__(16) float g_u[BB*NN*HID];     // same layout
__device__ __align__(16) float g_yprev[BB*NN];     // [b*NN+n]
__device__ __align__(16) float g_pooled[NN*C2C];
__device__ __align__(16) float g_fa[NN*DD];
__device__ __align__(16) float g_fb[NN*DD];

// ---------------- init: zero h / yprev each run ----------------
__global__ void init_kernel() {
    int i = blockIdx.x * blockDim.x + threadIdx.x;
    if (i < BB*NN*HID) g_h[i] = 0.f;
    if (i < BB*NN) g_yprev[i] = 0.f;
}

// ---------------- fused conv1+relu+conv2+relu+meanpool, one block per node ----------------
#define CT 512
__global__ void conv_pool_kernel(const float* __restrict__ x,
                                 const float* __restrict__ w1, const float* __restrict__ b1,
                                 const float* __restrict__ w2, const float* __restrict__ b2) {
    int n = blockIdx.x;
    const float* xs = x + n*TT;
    __shared__ float sw1[C1C*KW];
    __shared__ float sw2[C2C*C1C*KW];
    __shared__ float sb1[C1C], sb2[C2C];
    __shared__ float sx[CT + 2*(KW-1)];
    __shared__ float sc1[C1C][CT + KW - 1];
    int tid = threadIdx.x;
    if (tid < C1C*KW) sw1[tid] = w1[tid];
    for (int i = tid; i < C2C*C1C*KW; i += 256) sw2[i] = w2[i];
    if (tid < C1C) sb1[tid] = b1[tid];
    if (tid < C2C) sb2[tid] = b2[tid];

    float tacc[C2C];
#pragma unroll
    for (int c = 0; c < C2C; c++) tacc[c] = 0.f;

    for (int t0 = 0; t0 < T2L; t0 += CT) {
        int cnt = min(CT, T2L - t0);
        __syncthreads();
        for (int i = tid; i < cnt + 2*(KW-1); i += 256) sx[i] = xs[t0 + i];
        __syncthreads();
        for (int p = tid; p < cnt + KW - 1; p += 256) {
#pragma unroll
            for (int c = 0; c < C1C; c++) {
                float s = sb1[c];
#pragma unroll
                for (int k = 0; k < KW; k++) s += sx[p+k] * sw1[c*KW+k];
                sc1[c][p] = fmaxf(s, 0.f);
            }
        }
        __syncthreads();
        for (int q = tid; q < cnt; q += 256) {
            float acc[C2C];
#pragma unroll
            for (int c = 0; c < C2C; c++) acc[c] = sb2[c];
#pragma unroll
            for (int ci = 0; ci < C1C; ci++) {
#pragma unroll
                for (int k = 0; k < KW; k++) {
                    float v = sc1[ci][q+k];
#pragma unroll
                    for (int c = 0; c < C2C; c++) acc[c] += v * sw2[(c*C1C+ci)*KW + k];
                }
            }
#pragma unroll
            for (int c = 0; c < C2C; c++) tacc[c] += fmaxf(acc[c], 0.f);
        }
    }
    // deterministic tree reduce per channel
    __shared__ float sred[256];
    for (int c = 0; c < C2C; c++) {
        __syncthreads();
        sred[tid] = tacc[c];
        __syncthreads();
        for (int off = 128; off > 0; off >>= 1) {
            if (tid < off) sred[tid] += sred[tid+off];
            __syncthreads();
        }
        if (tid == 0) g_pooled[n*C2C + c] = sred[0] / (float)T2L;
    }
}

// ---------------- fc + fa/fb, one block (128 thr) per node ----------------
__global__ void fc_fab_kernel(const float* __restrict__ fcw, const float* __restrict__ fcb,
                              const float* __restrict__ Wa, const float* __restrict__ Wb) {
    int n = blockIdx.x;
    int d = threadIdx.x;
    __shared__ float sp[C2C];
    __shared__ float sf[DD];
    if (d < C2C) sp[d] = g_pooled[n*C2C + d];
    __syncthreads();
    float v = fcb[d];
#pragma unroll
    for (int c = 0; c < C2C; c++) v += sp[c] * fcw[c*DD + d];
    sf[d] = fmaxf(v, 0.f);
    __syncthreads();
    float a = 0.f, b = 0.f;
    for (int k = 0; k < DD; k++) {
        float fv = sf[k];
        a += fv * Wa[k*DD + d];
        b += fv * Wb[k*DD + d];
    }
    g_fa[n*DD + d] = a;
    g_fb[n*DD + d] = b;
}

// ---------------- edge MLP + gumbel hard mask ----------------
__global__ void edge_kernel(const float* __restrict__ b1v, const float* __restrict__ W2,
                            const float* __restrict__ b2v, const float* __restrict__ unoise,
                            float* __restrict__ mask) {
    __shared__ float sfa[16][DD+1], sfb[16][DD+1];
    __shared__ float sb1[DD], sw2[2*DD];
    int tid = threadIdx.x;
    int i0 = blockIdx.y * 16, j0 = blockIdx.x * 16;
    for (int idx = tid; idx < 16*DD; idx += 256) {
        int r = idx >> 7, c = idx & 127;
        sfa[r][c] = (i0 + r < NN) ? g_fa[(i0+r)*DD + c] : 0.f;
        sfb[r][c] = (j0 + r < NN) ? g_fb[(j0+r)*DD + c] : 0.f;
    }
    if (tid < DD) sb1[tid] = b1v[tid];
    if (tid < 2*DD) sw2[tid] = W2[tid];
    __syncthreads();
    int ti = tid >> 4, tj = tid & 15;
    int i = i0 + ti, j = j0 + tj;
    if (i < NN && j < NN) {
        float a0 = b2v[0], a1 = b2v[1];
#pragma unroll 4
        for (int k = 0; k < DD; k++) {
            float v = fmaxf(sfa[ti][k] + sfb[tj][k] + sb1[k], 0.f);
            a0 += v * sw2[2*k];
            a1 += v * sw2[2*k+1];
        }
        int e = i*NN + j;
        float u0 = unoise[2*e], u1 = unoise[2*e+1];
        float g0 = -logf(-logf(u0 + 1e-10f) + 1e-10f);
        float g1 = -logf(-logf(u1 + 1e-10f) + 1e-10f);
        float m = ((a0 + g0) >= (a1 + g1)) ? 1.f : 0.f;
        if (i == j) m = 0.f;
        mask[e] = m;
    }
}

// ---------------- row-normalize mask -> A (padded layout) ----------------
__global__ void rownorm_kernel(const float* __restrict__ mask) {
    int i = blockIdx.x;
    int tid = threadIdx.x;
    __shared__ float sred[256];
    float s = 0.f;
    for (int j = tid; j < NN; j += 256) s += mask[i*NN + j];
    sred[tid] = s;
    __syncthreads();
    for (int off = 128; off > 0; off >>= 1) {
        if (tid < off) sred[tid] += sred[tid+off];
        __syncthreads();
    }
    float inv = 1.f / (sred[0] + 1e-6f);
    for (int j = tid; j < NN; j += 256) g_A[i*KP + j] = mask[i*NN + j] * inv;
}

// ---------------- build cat = [x, h] in GEMM layout [node j][b*65+f] ----------------
__global__ void build_cat_kernel(const float* __restrict__ x, int bstride, int use_yprev) {
    int idx = blockIdx.x * blockDim.x + threadIdx.x;
    if (idx >= NN*BFCOLS) return;
    int n = idx / BFCOLS, c = idx % BFCOLS;
    int b = c / INF, f = c % INF;
    float v;
    if (f == 0) v = use_yprev ? g_yprev[b*NN + n] : x[b*bstride + n];
    else        v = g_h[(n*BB + b)*HID + (f-1)];
    g_cat[n*NPS + c] = v;
}

// ---------------- SGEMM: C[MP,NPS] = A[MP,KP] * X[KP,NPS], no guards (padded) ----------------
#define GBM 128
#define GBN 64
#define GBK 16
__global__ void sgemm_kernel(int which) {
    const float* __restrict__ X = which ? g_cat2 : g_cat;
    float* __restrict__ C = which ? g_agg2 : g_agg;
    __shared__ __align__(16) float As[GBK][GBM];
    __shared__ __align__(16) float Bs[GBK][GBN];
    int tid = threadIdx.x;
    int m0 = blockIdx.y * GBM, n0 = blockIdx.x * GBN;
    int aRow = tid >> 1, aCol = (tid & 1) * 8;
    int bRow = tid >> 4, bCol = (tid & 15) * 4;
    int ty = tid >> 4, tx = tid & 15;
    float acc[8][4];
#pragma unroll
    for (int i = 0; i < 8; i++)
#pragma unroll
        for (int j = 0; j < 4; j++) acc[i][j] = 0.f;

    for (int k0 = 0; k0 < KP; k0 += GBK) {
        float4 av0 = *(const float4*)&g_A[(m0+aRow)*KP + k0 + aCol];
        float4 av1 = *(const float4*)&g_A[(m0+aRow)*KP + k0 + aCol + 4];
        As[aCol+0][aRow] = av0.x; As[aCol+1][aRow] = av0.y;
        As[aCol+2][aRow] = av0.z; As[aCol+3][aRow] = av0.w;
        As[aCol+4][aRow] = av1.x; As[aCol+5][aRow] = av1.y;
        As[aCol+6][aRow] = av1.z; As[aCol+7][aRow] = av1.w;
        *(float4*)&Bs[bRow][bCol] = *(const float4*)&X[(k0+bRow)*NPS + n0 + bCol];
        __syncthreads();
#pragma unroll
        for (int k = 0; k < GBK; k++) {
            float ra[8], rb[4];
#pragma unroll
            for (int i = 0; i < 8; i++) ra[i] = As[k][ty*8 + i];
#pragma unroll
            for (int j = 0; j < 4; j++) rb[j] = Bs[k][tx*4 + j];
#pragma unroll
            for (int i = 0; i < 8; i++)
#pragma unroll
                for (int j = 0; j < 4; j++) acc[i][j] += ra[i] * rb[j];
        }
        __syncthreads();
    }
#pragma unroll
    for (int i = 0; i < 8; i++) {
        float4 o = make_float4(acc[i][0], acc[i][1], acc[i][2], acc[i][3]);
        *(float4*)&C[(m0 + ty*8 + i)*NPS + n0 + tx*4] = o;
    }
}

// ---------------- gates: ru = sigmoid(cat@W0 + agg@W1 + bru); build cat2; store u ----------------
// 512 threads, 64 rows x 128 cols per block, dynamic smem ~100KB
#define GATES_SMEM ((INF*DD*2 + 64*66*2) * 4)
__global__ void gates_kernel(const float* __restrict__ Wru0, const float* __restrict__ Wru1,
                             const float* __restrict__ bru) {
    extern __shared__ __align__(16) float sm[];
    float* sW0  = sm;                    // 65*128
    float* sW1  = sW0 + INF*DD;          // 65*128
    float* srow = sW1 + INF*DD;          // 64*66 (cat)
    float* sag  = srow + 64*66;          // 64*66 (agg)
    int tid = threadIdx.x;
    int r0 = blockIdx.x * 64;
    for (int i = tid; i < INF*DD; i += 512) { sW0[i] = Wru0[i]; sW1[i] = Wru1[i]; }
    for (int i = tid; i < 64*INF; i += 512) {
        int lr = i / INF, f = i % INF;
        int rid = r0 + lr, n = rid >> 4, b = rid & 15;
        srow[lr*66 + f] = g_cat[n*NPS + b*INF + f];
        sag [lr*66 + f] = g_agg[n*NPS + b*INF + f];
    }
    __syncthreads();
    int rt = tid >> 5;     // 0..15 -> rows rt*4..+3
    int ct = tid & 31;     // cols ct*4..+3
    float acc[4][4];
#pragma unroll
    for (int i = 0; i < 4; i++)
#pragma unroll
        for (int j = 0; j < 4; j++) acc[i][j] = bru[ct*4 + j];
    for (int f = 0; f < INF; f++) {
        float a[4], g[4];
#pragma unroll
        for (int i = 0; i < 4; i++) {
            a[i] = srow[(rt*4+i)*66 + f];
            g[i] = sag [(rt*4+i)*66 + f];
        }
        float4 w0 = *(const float4*)&sW0[f*DD + ct*4];
        float4 w1 = *(const float4*)&sW1[f*DD + ct*4];
#pragma unroll
        for (int i = 0; i < 4; i++) {
            acc[i][0] += a[i]*w0.x + g[i]*w1.x;
            acc[i][1] += a[i]*w0.y + g[i]*w1.y;
            acc[i][2] += a[i]*w0.z + g[i]*w1.z;
            acc[i][3] += a[i]*w0.w + g[i]*w1.w;
        }
    }
#pragma unroll
    for (int i = 0; i < 4; i++) {
        int lr = rt*4 + i, rid = r0 + lr, n = rid >> 4, b = rid & 15;
#pragma unroll
        for (int j = 0; j < 4; j++) {
            int c = ct*4 + j;
            float s = 1.f / (1.f + expf(-acc[i][j]));
            if (c < HID) {
                float hv = srow[lr*66 + 1 + c];
                g_cat2[n*NPS + b*INF + 1 + c] = s * hv;
            } else {
                g_u[rid*HID + (c - HID)] = s;
            }
        }
    }
    if (tid < 64) {
        int rid = r0 + tid, n = rid >> 4, b = rid & 15;
        g_cat2[n*NPS + b*INF] = srow[tid*66];    // x column
    }
}

// ---------------- update: c = tanh(cat2@Wc0 + agg2@Wc1 + bc); h = u*h + (1-u)*c ----------------
// 256 threads, 64 rows x 64 cols, dynamic smem ~67KB
#define UPD_SMEM ((INF*HID*2 + 64*66*2) * 4)
__global__ void update_kernel(const float* __restrict__ Wc0, const float* __restrict__ Wc1,
                              const float* __restrict__ bc) {
    extern __shared__ __align__(16) float sm[];
    float* sW0  = sm;                     // 65*64
    float* sW1  = sW0 + INF*HID;
    float* srow = sW1 + INF*HID;          // 64*66
    float* sag  = srow + 64*66;
    int tid = threadIdx.x;
    int r0 = blockIdx.x * 64;
    for (int i = tid; i < INF*HID; i += 256) { sW0[i] = Wc0[i]; sW1[i] = Wc1[i]; }
    for (int i = tid; i < 64*INF; i += 256) {
        int lr = i / INF, f = i % INF;
        int rid = r0 + lr, n = rid >> 4, b = rid & 15;
        srow[lr*66 + f] = g_cat2[n*NPS + b*INF + f];
        sag [lr*66 + f] = g_agg2[n*NPS + b*INF + f];
    }
    __syncthreads();
    int rt = tid >> 4;     // 0..15
    int ct = tid & 15;     // cols ct*4..+3
    float acc[4][4];
#pragma unroll
    for (int i = 0; i < 4; i++)
#pragma unroll
        for (int j = 0; j < 4; j++) acc[i][j] = bc[ct*4 + j];
    for (int f = 0; f < INF; f++) {
        float a[4], g[4];
#pragma unroll
        for (int i = 0; i < 4; i++) {
            a[i] = srow[(rt*4+i)*66 + f];
            g[i] = sag [(rt*4+i)*66 + f];
        }
        float4 w0 = *(const float4*)&sW0[f*HID + ct*4];
        float4 w1 = *(const float4*)&sW1[f*HID + ct*4];
#pragma unroll
        for (int i = 0; i < 4; i++) {
            acc[i][0] += a[i]*w0.x + g[i]*w1.x;
            acc[i][1] += a[i]*w0.y + g[i]*w1.y;
            acc[i][2] += a[i]*w0.z + g[i]*w1.z;
            acc[i][3] += a[i]*w0.w + g[i]*w1.w;
        }
    }
#pragma unroll
    for (int i = 0; i < 4; i++) {
        int lr = rt*4 + i, rid = r0 + lr;
#pragma unroll
        for (int j = 0; j < 4; j++) {
            int c = ct*4 + j;
            float cv = tanhf(acc[i][j]);
            float u = g_u[rid*HID + c];
            float hv = g_h[rid*HID + c];
            g_h[rid*HID + c] = u*hv + (1.f - u)*cv;
        }
    }
}

// ---------------- projection (decoder): y = h@proj_w + proj_b ----------------
__global__ void proj_kernel(const float* __restrict__ pw, const float* __restrict__ pb,
                            float* __restrict__ outp, int t) {
    int gw = (blockIdx.x * blockDim.x + threadIdx.x) >> 5;
    int lane = threadIdx.x & 31;
    if (gw >= BB*NN) return;
    int rid = gw;                        // rid = n*16+b
    float s = g_h[rid*HID + lane]*pw[lane] + g_h[rid*HID + 32 + lane]*pw[32 + lane];
#pragma unroll
    for (int off = 16; off > 0; off >>= 1) s += __shfl_down_sync(0xffffffffu, s, off);
    if (lane == 0) {
        int n = rid >> 4, b = rid & 15;
        float y = s + pb[0];
        g_yprev[b*NN + n] = y;
        outp[(b*HH + t)*NN + n] = y;
    }
}

// ---------------- loss: mean((outputs-targets)^2), single block deterministic ----------------
__global__ void loss_kernel(const float* __restrict__ outp, const float* __restrict__ targ,
                            float* __restrict__ lossout) {
    __shared__ double sred[256];
    int tid = threadIdx.x;
    double s = 0.0;
    for (int i = tid; i < BB*HH*NN; i += 256) {
        float d = outp[i] - targ[i];
        s += (double)d * (double)d;
    }
    sred[tid] = s;
    __syncthreads();
    for (int off = 128; off > 0; off >>= 1) {
        if (tid < off) sred[tid] += sred[tid+off];
        __syncthreads();
    }
    if (tid == 0) lossout[0] = (float)(sred[0] / (double)(BB*HH*NN));
}

// ---------------- host ----------------
extern "C" void kernel_launch(void* const* d_in, const int* in_sizes, int n_in,
                              void* d_out, int out_size) {
    const float* inputs  = (const float*)d_in[0];
    // d_in[1] entire_inputs
    const float* entire  = (const float*)d_in[1];
    const float* targets = (const float*)d_in[2];
    const float* unoise  = (const float*)d_in[3];
    const float* c1w = (const float*)d_in[4];
    const float* c1b = (const float*)d_in[5];
    const float* c2w = (const float*)d_in[6];
    const float* c2b = (const float*)d_in[7];
    const float* fcw = (const float*)d_in[8];
    const float* fcb = (const float*)d_in[9];
    const float* Wa  = (const float*)d_in[10];
    const float* Wb  = (const float*)d_in[11];
    const float* b1  = (const float*)d_in[12];
    const float* W2  = (const float*)d_in[13];
    const float* b2  = (const float*)d_in[14];
    const float* eWru0 = (const float*)d_in[15];
    const float* eWru1 = (const float*)d_in[16];
    const float* ebru  = (const float*)d_in[17];
    const float* eWc0  = (const float*)d_in[18];
    const float* eWc1  = (const float*)d_in[19];
    const float* ebc   = (const float*)d_in[20];
    const float* dWru0 = (const float*)d_in[21];
    const float* dWru1 = (const float*)d_in[22];
    const float* dbru  = (const float*)d_in[23];
    const float* dWc0  = (const float*)d_in[24];
    const float* dWc1  = (const float*)d_in[25];
    const float* dbc   = (const float*)d_in[26];
    const float* pw    = (const float*)d_in[27];
    const float* pb    = (const float*)d_in[28];

    float* out      = (float*)d_out;
    float* maskout  = out;                       // N*N
    float* outputs  = out + NN*NN;               // B*H*N
    float* lossout  = out + NN*NN + BB*HH*NN;    // 1

    // opt-in large dynamic smem (idempotent; set on correctness call, persists for capture)
    cudaFuncSetAttribute(gates_kernel,  cudaFuncAttributeMaxDynamicSharedMemorySize, GATES_SMEM);
    cudaFuncSetAttribute(update_kernel, cudaFuncAttributeMaxDynamicSharedMemorySize, UPD_SMEM);

    init_kernel<<<(BB*NN*HID + 255)/256, 256>>>();
    conv_pool_kernel<<<NN, 256>>>(entire, c1w, c1b, c2w, c2b);
    fc_fab_kernel<<<NN, DD>>>(fcw, fcb, Wa, Wb);
    dim3 eg(63, 63);
    edge_kernel<<<eg, 256>>>(b1, W2, b2, unoise, maskout);
    rownorm_kernel<<<NN, 256>>>(maskout);

    dim3 gg(NPS/GBN, MP/GBM);   // (17, 8)
    int bc_blocks = (NN*BFCOLS + 255)/256;

    // encoder
    for (int s = 0; s < SS; s++) {
        build_cat_kernel<<<bc_blocks, 256>>>(inputs + s*NN, SS*NN, 0);
        sgemm_kernel<<<gg, 256>>>(0);
        gates_kernel<<<BB*NN/64, 512, GATES_SMEM>>>(eWru0, eWru1, ebru);
        sgemm_kernel<<<gg, 256>>>(1);
        update_kernel<<<BB*NN/64, 256, UPD_SMEM>>>(eWc0, eWc1, ebc);
    }
    // decoder
    for (int t = 0; t < HH; t++) {
        build_cat_kernel<<<bc_blocks, 256>>>(inputs, NN, 1);   // x from g_yprev
        sgemm_kernel<<<gg, 256>>>(0);
        gates_kernel<<<BB*NN/64, 512, GATES_SMEM>>>(dWru0, dWru1, dbru);
        sgemm_kernel<<<gg, 256>>>(1);
        update_kernel<<<BB*NN/64, 256, UPD_SMEM>>>(dWc0, dWc1, dbc);
        proj_kernel<<<(BB*NN*32 + 255)/256, 256>>>(pw, pb, outputs, t);
    }
    loss_kernel<<<1, 256>>>(outputs, targets, lossout);
}

// round 12
// speedup vs baseline: 1.0621x; 1.0621x over previous
#include <cuda_runtime.h>
#include <math.h>

// ---------------- problem dims ----------------
#define NN 1000
#define TT 4000
#define BB 16
#define SS 12
#define HH 12
#define C1C 8
#define C2C 16
#define KW 10
#define DD 128
#define HID 64
#define INF 65           // 1 + HID
#define T1L (TT-KW+1)    // 3991
#define T2L (T1L-KW+1)   // 3982
#define BFCOLS (BB*INF)  // 1040

// padded GEMM dims (zero-pad regions are never written -> stay 0)
#define MP 1024
#define KP 1024
#define NPS 1088         // padded column stride (17 * 64)

// ---------------- scratch (device globals; no allocation allowed) ----------------
__device__ __align__(16) float g_A[MP*KP];
__device__ __align__(16) float g_cat[KP*NPS];
__device__ __align__(16) float g_cat2[KP*NPS];
__device__ __align__(16) float g_agg[MP*NPS];
__device__ __align__(16) float g_agg2[MP*NPS];
__device__ __align__(16) float g_h[BB*NN*HID];     // layout: rid = n*16+b, [rid][HID]
__device__ __align__(16) float g_u[BB*NN*HID];     // same layout
__device__ __align__(16) float g_yprev[BB*NN];     // [b*NN+n]
__device__ __align__(16) float g_pooled[NN*C2C];
__device__ __align__(16) float g_fa[NN*DD];
__device__ __align__(16) float g_fb[NN*DD];

// ---------------- init: zero h / yprev / cat each run (graph-replay determinism) ----------------
__global__ void init_kernel() {
    int i = blockIdx.x * blockDim.x + threadIdx.x;
    if (i < KP*NPS) g_cat[i] = 0.f;
    if (i < BB*NN*HID) g_h[i] = 0.f;
    if (i < BB*NN) g_yprev[i] = 0.f;
}

// ---------------- fused conv1+relu+conv2+relu+meanpool, one block per node ----------------
#define CT 512
__global__ void conv_pool_kernel(const float* __restrict__ x,
                                 const float* __restrict__ w1, const float* __restrict__ b1,
                                 const float* __restrict__ w2, const float* __restrict__ b2) {
    int n = blockIdx.x;
    const float* xs = x + n*TT;
    __shared__ float sw1[C1C*KW];
    __shared__ float sw2[C2C*C1C*KW];
    __shared__ float sb1[C1C], sb2[C2C];
    __shared__ float sx[CT + 2*(KW-1)];
    __shared__ float sc1[C1C][CT + KW - 1];
    int tid = threadIdx.x;
    if (tid < C1C*KW) sw1[tid] = w1[tid];
    for (int i = tid; i < C2C*C1C*KW; i += 256) sw2[i] = w2[i];
    if (tid < C1C) sb1[tid] = b1[tid];
    if (tid < C2C) sb2[tid] = b2[tid];

    float tacc[C2C];
#pragma unroll
    for (int c = 0; c < C2C; c++) tacc[c] = 0.f;

    for (int t0 = 0; t0 < T2L; t0 += CT) {
        int cnt = min(CT, T2L - t0);
        __syncthreads();
        for (int i = tid; i < cnt + 2*(KW-1); i += 256) sx[i] = xs[t0 + i];
        __syncthreads();
        for (int p = tid; p < cnt + KW - 1; p += 256) {
#pragma unroll
            for (int c = 0; c < C1C; c++) {
                float s = sb1[c];
#pragma unroll
                for (int k = 0; k < KW; k++) s += sx[p+k] * sw1[c*KW+k];
                sc1[c][p] = fmaxf(s, 0.f);
            }
        }
        __syncthreads();
        for (int q = tid; q < cnt; q += 256) {
            float acc[C2C];
#pragma unroll
            for (int c = 0; c < C2C; c++) acc[c] = sb2[c];
#pragma unroll
            for (int ci = 0; ci < C1C; ci++) {
#pragma unroll
                for (int k = 0; k < KW; k++) {
                    float v = sc1[ci][q+k];
#pragma unroll
                    for (int c = 0; c < C2C; c++) acc[c] += v * sw2[(c*C1C+ci)*KW + k];
                }
            }
#pragma unroll
            for (int c = 0; c < C2C; c++) tacc[c] += fmaxf(acc[c], 0.f);
        }
    }
    __shared__ float sred[256];
    for (int c = 0; c < C2C; c++) {
        __syncthreads();
        sred[tid] = tacc[c];
        __syncthreads();
        for (int off = 128; off > 0; off >>= 1) {
            if (tid < off) sred[tid] += sred[tid+off];
            __syncthreads();
        }
        if (tid == 0) g_pooled[n*C2C + c] = sred[0] / (float)T2L;
    }
}

// ---------------- fc + fa/fb, one block (128 thr) per node ----------------
__global__ void fc_fab_kernel(const float* __restrict__ fcw, const float* __restrict__ fcb,
                              const float* __restrict__ Wa, const float* __restrict__ Wb) {
    int n = blockIdx.x;
    int d = threadIdx.x;
    __shared__ float sp[C2C];
    __shared__ float sf[DD];
    if (d < C2C) sp[d] = g_pooled[n*C2C + d];
    __syncthreads();
    float v = fcb[d];
#pragma unroll
    for (int c = 0; c < C2C; c++) v += sp[c] * fcw[c*DD + d];
    sf[d] = fmaxf(v, 0.f);
    __syncthreads();
    float a = 0.f, b = 0.f;
    for (int k = 0; k < DD; k++) {
        float fv = sf[k];
        a += fv * Wa[k*DD + d];
        b += fv * Wb[k*DD + d];
    }
    g_fa[n*DD + d] = a;
    g_fb[n*DD + d] = b;
}

// ---------------- edge MLP + gumbel hard mask ----------------
__global__ void edge_kernel(const float* __restrict__ b1v, const float* __restrict__ W2,
                            const float* __restrict__ b2v, const float* __restrict__ unoise,
                            float* __restrict__ mask) {
    __shared__ float sfa[16][DD+1], sfb[16][DD+1];
    __shared__ float sb1[DD], sw2[2*DD];
    int tid = threadIdx.x;
    int i0 = blockIdx.y * 16, j0 = blockIdx.x * 16;
    for (int idx = tid; idx < 16*DD; idx += 256) {
        int r = idx >> 7, c = idx & 127;
        sfa[r][c] = (i0 + r < NN) ? g_fa[(i0+r)*DD + c] : 0.f;
        sfb[r][c] = (j0 + r < NN) ? g_fb[(j0+r)*DD + c] : 0.f;
    }
    if (tid < DD) sb1[tid] = b1v[tid];
    if (tid < 2*DD) sw2[tid] = W2[tid];
    __syncthreads();
    int ti = tid >> 4, tj = tid & 15;
    int i = i0 + ti, j = j0 + tj;
    if (i < NN && j < NN) {
        float a0 = b2v[0], a1 = b2v[1];
#pragma unroll 4
        for (int k = 0; k < DD; k++) {
            float v = fmaxf(sfa[ti][k] + sfb[tj][k] + sb1[k], 0.f);
            a0 += v * sw2[2*k];
            a1 += v * sw2[2*k+1];
        }
        int e = i*NN + j;
        float u0 = unoise[2*e], u1 = unoise[2*e+1];
        float g0 = -logf(-logf(u0 + 1e-10f) + 1e-10f);
        float g1 = -logf(-logf(u1 + 1e-10f) + 1e-10f);
        float m = ((a0 + g0) >= (a1 + g1)) ? 1.f : 0.f;
        if (i == j) m = 0.f;
        mask[e] = m;
    }
}

// ---------------- row-normalize mask -> A (padded layout) ----------------
__global__ void rownorm_kernel(const float* __restrict__ mask) {
    int i = blockIdx.x;
    int tid = threadIdx.x;
    __shared__ float sred[256];
    float s = 0.f;
    for (int j = tid; j < NN; j += 256) s += mask[i*NN + j];
    sred[tid] = s;
    __syncthreads();
    for (int off = 128; off > 0; off >>= 1) {
        if (tid < off) sred[tid] += sred[tid+off];
        __syncthreads();
    }
    float inv = 1.f / (sred[0] + 1e-6f);
    for (int j = tid; j < NN; j += 256) g_A[i*KP + j] = mask[i*NN + j] * inv;
}

// ---------------- set x column of g_cat ----------------
__global__ void set_x_kernel(const float* __restrict__ x, int bstride, int use_yprev) {
    int idx = blockIdx.x * blockDim.x + threadIdx.x;
    if (idx >= NN*BB) return;
    int n = idx >> 4, b = idx & 15;
    float v = use_yprev ? g_yprev[b*NN + n] : x[b*bstride + n];
    g_cat[n*NPS + b*INF] = v;
}

// ---------------- SGEMM: C[MP,NPS] = A[MP,KP] * X[KP,NPS], 64x64 tiles, double-buffered ----------------
#define TBM 64
#define TBN 64
#define TBK 16
#define APAD 68
__global__ void sgemm_kernel(int which) {
    const float* __restrict__ X = which ? g_cat2 : g_cat;
    float* __restrict__ C = which ? g_agg2 : g_agg;
    __shared__ __align__(16) float As[2][TBK][APAD];   // transposed: [k][m]
    __shared__ __align__(16) float Bs[2][TBK][TBN];
    int tid = threadIdx.x;
    int m0 = blockIdx.y * TBM, n0 = blockIdx.x * TBN;
    int aRow = tid >> 2, aCol = (tid & 3) * 4;     // A load: row aRow, k-cols aCol..aCol+3
    int bRow = tid >> 4, bCol = (tid & 15) * 4;    // B load: k-row bRow, cols bCol..+3
    int ty = tid >> 4, tx = tid & 15;              // compute: rows ty*4..+3, cols tx*4..+3

    const float* Aptr = &g_A[(m0 + aRow)*KP + aCol];
    const float* Bptr = &X[bRow*NPS + n0 + bCol];

    float4 a4 = *(const float4*)Aptr;
    float4 b4 = *(const float4*)Bptr;
    As[0][aCol+0][aRow] = a4.x; As[0][aCol+1][aRow] = a4.y;
    As[0][aCol+2][aRow] = a4.z; As[0][aCol+3][aRow] = a4.w;
    *(float4*)&Bs[0][bRow][bCol] = b4;
    __syncthreads();

    float acc[4][4];
#pragma unroll
    for (int i = 0; i < 4; i++)
#pragma unroll
        for (int j = 0; j < 4; j++) acc[i][j] = 0.f;

    int buf = 0;
    for (int k0 = TBK; k0 <= KP; k0 += TBK) {
        if (k0 < KP) {
            a4 = *(const float4*)(Aptr + k0);
            b4 = *(const float4*)(Bptr + (size_t)k0*NPS);
        }
#pragma unroll
        for (int k = 0; k < TBK; k++) {
            float4 ra = *(const float4*)&As[buf][k][ty*4];
            float4 rb = *(const float4*)&Bs[buf][k][tx*4];
            acc[0][0] += ra.x*rb.x; acc[0][1] += ra.x*rb.y; acc[0][2] += ra.x*rb.z; acc[0][3] += ra.x*rb.w;
            acc[1][0] += ra.y*rb.x; acc[1][1] += ra.y*rb.y; acc[1][2] += ra.y*rb.z; acc[1][3] += ra.y*rb.w;
            acc[2][0] += ra.z*rb.x; acc[2][1] += ra.z*rb.y; acc[2][2] += ra.z*rb.z; acc[2][3] += ra.z*rb.w;
            acc[3][0] += ra.w*rb.x; acc[3][1] += ra.w*rb.y; acc[3][2] += ra.w*rb.z; acc[3][3] += ra.w*rb.w;
        }
        if (k0 < KP) {
            int nb = buf ^ 1;
            As[nb][aCol+0][aRow] = a4.x; As[nb][aCol+1][aRow] = a4.y;
            As[nb][aCol+2][aRow] = a4.z; As[nb][aCol+3][aRow] = a4.w;
            *(float4*)&Bs[nb][bRow][bCol] = b4;
            __syncthreads();
            buf = nb;
        }
    }
#pragma unroll
    for (int i = 0; i < 4; i++) {
        float4 o = make_float4(acc[i][0], acc[i][1], acc[i][2], acc[i][3]);
        *(float4*)&C[(size_t)(m0 + ty*4 + i)*NPS + n0 + tx*4] = o;
    }
}

// ---------------- gates: ru = sigmoid(cat@W0 + agg@W1 + bru); build cat2; store u ----------------
#define GATES_SMEM ((INF*DD*2 + 64*66*2) * 4)
__global__ void gates_kernel(const float* __restrict__ Wru0, const float* __restrict__ Wru1,
                             const float* __restrict__ bru) {
    extern __shared__ __align__(16) float sm[];
    float* sW0  = sm;                    // 65*128
    float* sW1  = sW0 + INF*DD;          // 65*128
    float* srow = sW1 + INF*DD;          // 64*66 (cat)
    float* sag  = srow + 64*66;          // 64*66 (agg)
    int tid = threadIdx.x;
    int r0 = blockIdx.x * 64;
    for (int i = tid; i < INF*DD; i += 512) { sW0[i] = Wru0[i]; sW1[i] = Wru1[i]; }
    for (int i = tid; i < 64*INF; i += 512) {
        int lr = i / INF, f = i % INF;
        int rid = r0 + lr, n = rid >> 4, b = rid & 15;
        srow[lr*66 + f] = g_cat[n*NPS + b*INF + f];
        sag [lr*66 + f] = g_agg[n*NPS + b*INF + f];
    }
    __syncthreads();
    int rt = tid >> 5;
    int ct = tid & 31;
    float acc[4][4];
#pragma unroll
    for (int i = 0; i < 4; i++)
#pragma unroll
        for (int j = 0; j < 4; j++) acc[i][j] = bru[ct*4 + j];
    for (int f = 0; f < INF; f++) {
        float a[4], g[4];
#pragma unroll
        for (int i = 0; i < 4; i++) {
            a[i] = srow[(rt*4+i)*66 + f];
            g[i] = sag [(rt*4+i)*66 + f];
        }
        float4 w0 = *(const float4*)&sW0[f*DD + ct*4];
        float4 w1 = *(const float4*)&sW1[f*DD + ct*4];
#pragma unroll
        for (int i = 0; i < 4; i++) {
            acc[i][0] += a[i]*w0.x + g[i]*w1.x;
            acc[i][1] += a[i]*w0.y + g[i]*w1.y;
            acc[i][2] += a[i]*w0.z + g[i]*w1.z;
            acc[i][3] += a[i]*w0.w + g[i]*w1.w;
        }
    }
#pragma unroll
    for (int i = 0; i < 4; i++) {
        int lr = rt*4 + i, rid = r0 + lr, n = rid >> 4, b = rid & 15;
#pragma unroll
        for (int j = 0; j < 4; j++) {
            int c = ct*4 + j;
            float s = 1.f / (1.f + expf(-acc[i][j]));
            if (c < HID) {
                float hv = srow[lr*66 + 1 + c];
                g_cat2[n*NPS + b*INF + 1 + c] = s * hv;
            } else {
                g_u[rid*HID + (c - HID)] = s;
            }
        }
    }
    if (tid < 64) {
        int rid = r0 + tid, n = rid >> 4, b = rid & 15;
        g_cat2[n*NPS + b*INF] = srow[tid*66];    // x column
    }
}

// ---------------- update: c = tanh(cat2@Wc0 + agg2@Wc1 + bc); h = u*h + (1-u)*c ----------------
// also writes new h directly into g_cat's h-columns for the next step
#define UPD_SMEM ((INF*HID*2 + 64*66*2) * 4)
__global__ void update_kernel(const float* __restrict__ Wc0, const float* __restrict__ Wc1,
                              const float* __restrict__ bc) {
    extern __shared__ __align__(16) float sm[];
    float* sW0  = sm;                     // 65*64
    float* sW1  = sW0 + INF*HID;
    float* srow = sW1 + INF*HID;          // 64*66
    float* sag  = srow + 64*66;
    int tid = threadIdx.x;
    int r0 = blockIdx.x * 64;
    for (int i = tid; i < INF*HID; i += 256) { sW0[i] = Wc0[i]; sW1[i] = Wc1[i]; }
    for (int i = tid; i < 64*INF; i += 256) {
        int lr = i / INF, f = i % INF;
        int rid = r0 + lr, n = rid >> 4, b = rid & 15;
        srow[lr*66 + f] = g_cat2[n*NPS + b*INF + f];
        sag [lr*66 + f] = g_agg2[n*NPS + b*INF + f];
    }
    __syncthreads();
    int rt = tid >> 4;
    int ct = tid & 15;
    float acc[4][4];
#pragma unroll
    for (int i = 0; i < 4; i++)
#pragma unroll
        for (int j = 0; j < 4; j++) acc[i][j] = bc[ct*4 + j];
    for (int f = 0; f < INF; f++) {
        float a[4], g[4];
#pragma unroll
        for (int i = 0; i < 4; i++) {
            a[i] = srow[(rt*4+i)*66 + f];
            g[i] = sag [(rt*4+i)*66 + f];
        }
        float4 w0 = *(const float4*)&sW0[f*HID + ct*4];
        float4 w1 = *(const float4*)&sW1[f*HID + ct*4];
#pragma unroll
        for (int i = 0; i < 4; i++) {
            acc[i][0] += a[i]*w0.x + g[i]*w1.x;
            acc[i][1] += a[i]*w0.y + g[i]*w1.y;
            acc[i][2] += a[i]*w0.z + g[i]*w1.z;
            acc[i][3] += a[i]*w0.w + g[i]*w1.w;
        }
    }
#pragma unroll
    for (int i = 0; i < 4; i++) {
        int lr = rt*4 + i, rid = r0 + lr, n = rid >> 4, b = rid & 15;
#pragma unroll
        for (int j = 0; j < 4; j++) {
            int c = ct*4 + j;
            float cv = tanhf(acc[i][j]);
            float u = g_u[rid*HID + c];
            float hv = g_h[rid*HID + c];
            float hn = u*hv + (1.f - u)*cv;
            g_h[rid*HID + c] = hn;
            g_cat[n*NPS + b*INF + 1 + c] = hn;   // feed next step's cat directly
        }
    }
}

// ---------------- projection (decoder): y = h@proj_w + proj_b ----------------
__global__ void proj_kernel(const float* __restrict__ pw, const float* __restrict__ pb,
                            float* __restrict__ outp, int t) {
    int gw = (blockIdx.x * blockDim.x + threadIdx.x) >> 5;
    int lane = threadIdx.x & 31;
    if (gw >= BB*NN) return;
    int rid = gw;                        // rid = n*16+b
    float s = g_h[rid*HID + lane]*pw[lane] + g_h[rid*HID + 32 + lane]*pw[32 + lane];
#pragma unroll
    for (int off = 16; off > 0; off >>= 1) s += __shfl_down_sync(0xffffffffu, s, off);
    if (lane == 0) {
        int n = rid >> 4, b = rid & 15;
        float y = s + pb[0];
        g_yprev[b*NN + n] = y;
        outp[(b*HH + t)*NN + n] = y;
    }
}

// ---------------- loss: mean((outputs-targets)^2), single block deterministic ----------------
__global__ void loss_kernel(const float* __restrict__ outp, const float* __restrict__ targ,
                            float* __restrict__ lossout) {
    __shared__ double sred[256];
    int tid = threadIdx.x;
    double s = 0.0;
    for (int i = tid; i < BB*HH*NN; i += 256) {
        float d = outp[i] - targ[i];
        s += (double)d * (double)d;
    }
    sred[tid] = s;
    __syncthreads();
    for (int off = 128; off > 0; off >>= 1) {
        if (tid < off) sred[tid] += sred[tid+off];
        __syncthreads();
    }
    if (tid == 0) lossout[0] = (float)(sred[0] / (double)(BB*HH*NN));
}

// ---------------- host ----------------
extern "C" void kernel_launch(void* const* d_in, const int* in_sizes, int n_in,
                              void* d_out, int out_size) {
    const float* inputs  = (const float*)d_in[0];
    const float* entire  = (const float*)d_in[1];
    const float* targets = (const float*)d_in[2];
    const float* unoise  = (const float*)d_in[3];
    const float* c1w = (const float*)d_in[4];
    const float* c1b = (const float*)d_in[5];
    const float* c2w = (const float*)d_in[6];
    const float* c2b = (const float*)d_in[7];
    const float* fcw = (const float*)d_in[8];
    const float* fcb = (const float*)d_in[9];
    const float* Wa  = (const float*)d_in[10];
    const float* Wb  = (const float*)d_in[11];
    const float* b1  = (const float*)d_in[12];
    const float* W2  = (const float*)d_in[13];
    const float* b2  = (const float*)d_in[14];
    const float* eWru0 = (const float*)d_in[15];
    const float* eWru1 = (const float*)d_in[16];
    const float* ebru  = (const float*)d_in[17];
    const float* eWc0  = (const float*)d_in[18];
    const float* eWc1  = (const float*)d_in[19];
    const float* ebc   = (const float*)d_in[20];
    const float* dWru0 = (const float*)d_in[21];
    const float* dWru1 = (const float*)d_in[22];
    const float* dbru  = (const float*)d_in[23];
    const float* dWc0  = (const float*)d_in[24];
    const float* dWc1  = (const float*)d_in[25];
    const float* dbc   = (const float*)d_in[26];
    const float* pw    = (const float*)d_in[27];
    const float* pb    = (const float*)d_in[28];

    float* out      = (float*)d_out;
    float* maskout  = out;                       // N*N
    float* outputs  = out + NN*NN;               // B*H*N
    float* lossout  = out + NN*NN + BB*HH*NN;    // 1

    cudaFuncSetAttribute(gates_kernel,  cudaFuncAttributeMaxDynamicSharedMemorySize, GATES_SMEM);
    cudaFuncSetAttribute(update_kernel, cudaFuncAttributeMaxDynamicSharedMemorySize, UPD_SMEM);

    init_kernel<<<(KP*NPS + 255)/256, 256>>>();
    conv_pool_kernel<<<NN, 256>>>(entire, c1w, c1b, c2w, c2b);
    fc_fab_kernel<<<NN, DD>>>(fcw, fcb, Wa, Wb);
    dim3 eg(63, 63);
    edge_kernel<<<eg, 256>>>(b1, W2, b2, unoise, maskout);
    rownorm_kernel<<<NN, 256>>>(maskout);

    dim3 gg(NPS/TBN, MP/TBM);   // (17, 16) = 272 blocks
    int sx_blocks = (NN*BB + 255)/256;

    // encoder
    for (int s = 0; s < SS; s++) {
        set_x_kernel<<<sx_blocks, 256>>>(inputs + s*NN, SS*NN, 0);
        sgemm_kernel<<<gg, 256>>>(0);
        gates_kernel<<<BB*NN/64, 512, GATES_SMEM>>>(eWru0, eWru1, ebru);
        sgemm_kernel<<<gg, 256>>>(1);
        update_kernel<<<BB*NN/64, 256, UPD_SMEM>>>(eWc0, eWc1, ebc);
    }
    // decoder
    for (int t = 0; t < HH; t++) {
        set_x_kernel<<<sx_blocks, 256>>>(inputs, NN, 1);   // x from g_yprev
        sgemm_kernel<<<gg, 256>>>(0);
        gates_kernel<<<BB*NN/64, 512, GATES_SMEM>>>(dWru0, dWru1, dbru);
        sgemm_kernel<<<gg, 256>>>(1);
        update_kernel<<<BB*NN/64, 256, UPD_SMEM>>>(dWc0, dWc1, dbc);
        proj_kernel<<<(BB*NN*32 + 255)/256, 256>>>(pw, pb, outputs, t);
    }
    loss_kernel<<<1, 256>>>(outputs, targets, lossout);
}

// round 13
// speedup vs baseline: 1.2453x; 1.1725x over previous
#include <cuda_runtime.h>
#include <math.h>
#include <stdint.h>

// ---------------- problem dims ----------------
#define NN 1000
#define TT 4000
#define BB 16
#define SS 12
#define HH 12
#define C1C 8
#define C2C 16
#define KW 10
#define DD 128
#define HID 64
#define INF 65           // 1 + HID
#define T1L (TT-KW+1)    // 3991
#define T2L (T1L-KW+1)   // 3982

// padded GEMM dims (zero-pad regions are never written -> stay 0)
#define MP 1024
#define KP 1024
#define NPS 1088         // padded column stride (17 * 64)

// ---------------- scratch (device globals; no allocation allowed) ----------------
__device__ __align__(16) float g_A[MP*KP];
__device__ __align__(16) float g_cat[KP*NPS];
__device__ __align__(16) float g_cat2[KP*NPS];
__device__ __align__(16) float g_agg[MP*NPS];
__device__ __align__(16) float g_agg2[MP*NPS];
__device__ __align__(16) float g_h[BB*NN*HID];     // layout: rid = n*16+b, [rid][HID]
__device__ __align__(16) float g_u[BB*NN*HID];     // same layout
__device__ __align__(16) float g_yprev[BB*NN];     // [b*NN+n]
__device__ __align__(16) float g_pooled[NN*C2C];
__device__ __align__(16) float g_fa[NN*DD];
__device__ __align__(16) float g_fb[NN*DD];

// ---------------- init: zero h / yprev / cat each run (graph-replay determinism) ----------------
__global__ void init_kernel() {
    int i = blockIdx.x * blockDim.x + threadIdx.x;
    if (i < KP*NPS) g_cat[i] = 0.f;
    if (i < BB*NN*HID) g_h[i] = 0.f;
    if (i < BB*NN) g_yprev[i] = 0.f;
}

// ---------------- fused conv1+relu+conv2+relu+meanpool, one block per node ----------------
#define CT 512
__global__ void conv_pool_kernel(const float* __restrict__ x,
                                 const float* __restrict__ w1, const float* __restrict__ b1,
                                 const float* __restrict__ w2, const float* __restrict__ b2) {
    int n = blockIdx.x;
    const float* xs = x + n*TT;
    __shared__ float sw1[C1C*KW];
    __shared__ float sw2[C2C*C1C*KW];
    __shared__ float sb1[C1C], sb2[C2C];
    __shared__ float sx[CT + 2*(KW-1)];
    __shared__ float sc1[C1C][CT + KW - 1];
    int tid = threadIdx.x;
    if (tid < C1C*KW) sw1[tid] = w1[tid];
    for (int i = tid; i < C2C*C1C*KW; i += 256) sw2[i] = w2[i];
    if (tid < C1C) sb1[tid] = b1[tid];
    if (tid < C2C) sb2[tid] = b2[tid];

    float tacc[C2C];
#pragma unroll
    for (int c = 0; c < C2C; c++) tacc[c] = 0.f;

    for (int t0 = 0; t0 < T2L; t0 += CT) {
        int cnt = min(CT, T2L - t0);
        __syncthreads();
        for (int i = tid; i < cnt + 2*(KW-1); i += 256) sx[i] = xs[t0 + i];
        __syncthreads();
        for (int p = tid; p < cnt + KW - 1; p += 256) {
#pragma unroll
            for (int c = 0; c < C1C; c++) {
                float s = sb1[c];
#pragma unroll
                for (int k = 0; k < KW; k++) s += sx[p+k] * sw1[c*KW+k];
                sc1[c][p] = fmaxf(s, 0.f);
            }
        }
        __syncthreads();
        for (int q = tid; q < cnt; q += 256) {
            float acc[C2C];
#pragma unroll
            for (int c = 0; c < C2C; c++) acc[c] = sb2[c];
#pragma unroll
            for (int ci = 0; ci < C1C; ci++) {
#pragma unroll
                for (int k = 0; k < KW; k++) {
                    float v = sc1[ci][q+k];
#pragma unroll
                    for (int c = 0; c < C2C; c++) acc[c] += v * sw2[(c*C1C+ci)*KW + k];
                }
            }
#pragma unroll
            for (int c = 0; c < C2C; c++) tacc[c] += fmaxf(acc[c], 0.f);
        }
    }
    __shared__ float sred[256];
    for (int c = 0; c < C2C; c++) {
        __syncthreads();
        sred[tid] = tacc[c];
        __syncthreads();
        for (int off = 128; off > 0; off >>= 1) {
            if (tid < off) sred[tid] += sred[tid+off];
            __syncthreads();
        }
        if (tid == 0) g_pooled[n*C2C + c] = sred[0] / (float)T2L;
    }
}

// ---------------- fc + fa/fb, one block (128 thr) per node ----------------
__global__ void fc_fab_kernel(const float* __restrict__ fcw, const float* __restrict__ fcb,
                              const float* __restrict__ Wa, const float* __restrict__ Wb) {
    int n = blockIdx.x;
    int d = threadIdx.x;
    __shared__ float sp[C2C];
    __shared__ float sf[DD];
    if (d < C2C) sp[d] = g_pooled[n*C2C + d];
    __syncthreads();
    float v = fcb[d];
#pragma unroll
    for (int c = 0; c < C2C; c++) v += sp[c] * fcw[c*DD + d];
    sf[d] = fmaxf(v, 0.f);
    __syncthreads();
    float a = 0.f, b = 0.f;
    for (int k = 0; k < DD; k++) {
        float fv = sf[k];
        a += fv * Wa[k*DD + d];
        b += fv * Wb[k*DD + d];
    }
    g_fa[n*DD + d] = a;
    g_fb[n*DD + d] = b;
}

// ---------------- edge MLP + gumbel hard mask ----------------
__global__ void edge_kernel(const float* __restrict__ b1v, const float* __restrict__ W2,
                            const float* __restrict__ b2v, const float* __restrict__ unoise,
                            float* __restrict__ mask) {
    __shared__ float sfa[16][DD+1], sfb[16][DD+1];
    __shared__ float sb1[DD], sw2[2*DD];
    int tid = threadIdx.x;
    int i0 = blockIdx.y * 16, j0 = blockIdx.x * 16;
    for (int idx = tid; idx < 16*DD; idx += 256) {
        int r = idx >> 7, c = idx & 127;
        sfa[r][c] = (i0 + r < NN) ? g_fa[(i0+r)*DD + c] : 0.f;
        sfb[r][c] = (j0 + r < NN) ? g_fb[(j0+r)*DD + c] : 0.f;
    }
    if (tid < DD) sb1[tid] = b1v[tid];
    if (tid < 2*DD) sw2[tid] = W2[tid];
    __syncthreads();
    int ti = tid >> 4, tj = tid & 15;
    int i = i0 + ti, j = j0 + tj;
    if (i < NN && j < NN) {
        float a0 = b2v[0], a1 = b2v[1];
#pragma unroll 4
        for (int k = 0; k < DD; k++) {
            float v = fmaxf(sfa[ti][k] + sfb[tj][k] + sb1[k], 0.f);
            a0 += v * sw2[2*k];
            a1 += v * sw2[2*k+1];
        }
        int e = i*NN + j;
        float u0 = unoise[2*e], u1 = unoise[2*e+1];
        float g0 = -logf(-logf(u0 + 1e-10f) + 1e-10f);
        float g1 = -logf(-logf(u1 + 1e-10f) + 1e-10f);
        float m = ((a0 + g0) >= (a1 + g1)) ? 1.f : 0.f;
        if (i == j) m = 0.f;
        mask[e] = m;
    }
}

// ---------------- row-normalize mask -> A (padded layout, pre-rounded to tf32) ----------------
__global__ void rownorm_kernel(const float* __restrict__ mask) {
    int i = blockIdx.x;
    int tid = threadIdx.x;
    __shared__ float sred[256];
    float s = 0.f;
    for (int j = tid; j < NN; j += 256) s += mask[i*NN + j];
    sred[tid] = s;
    __syncthreads();
    for (int off = 128; off > 0; off >>= 1) {
        if (tid < off) sred[tid] += sred[tid+off];
        __syncthreads();
    }
    float inv = 1.f / (sred[0] + 1e-6f);
    for (int j = tid; j < NN; j += 256) {
        float v = mask[i*NN + j] * inv;
        uint32_t t;
        asm("cvt.rna.tf32.f32 %0, %1;" : "=r"(t) : "f"(v));
        g_A[i*KP + j] = __uint_as_float(t);
    }
}

// ---------------- set x column of g_cat ----------------
__global__ void set_x_kernel(const float* __restrict__ x, int bstride, int use_yprev) {
    int idx = blockIdx.x * blockDim.x + threadIdx.x;
    if (idx >= NN*BB) return;
    int n = idx >> 4, b = idx & 15;
    float v = use_yprev ? g_yprev[b*NN + n] : x[b*bstride + n];
    g_cat[n*NPS + b*INF] = v;
}

// ---------------- tf32 tensor-core GEMM: C[MP,NPS] = A * X ----------------
// CTA tile 128x64, 8 warps as 4(m) x 2(n), warp tile 32x32, mma.m16n8k8.tf32
#define APAD 36
#define BPAD 72
#define ASZ (128*APAD)
#define BSZ (32*BPAD)
#define MMA_SMEM ((2*ASZ + 2*BSZ) * 4)
__global__ void __launch_bounds__(256) mma_gemm_kernel(int which) {
    const float* __restrict__ X = which ? g_cat2 : g_cat;
    float* __restrict__ C = which ? g_agg2 : g_agg;
    extern __shared__ __align__(16) float sm[];
    float* Abase = sm;                 // 2 x [128][APAD]
    float* Bbase = sm + 2*ASZ;         // 2 x [32][BPAD]

    int tid  = threadIdx.x;
    int lane = tid & 31;
    int wid  = tid >> 5;
    int wm = wid >> 1;                 // 0..3
    int wn = wid & 1;                  // 0..1
    int lr = lane >> 2;                // 0..7
    int lc = lane & 3;                 // 0..3
    int m0 = blockIdx.y * 128, n0 = blockIdx.x * 64;

    float acc[2][4][4];
#pragma unroll
    for (int mi = 0; mi < 2; mi++)
#pragma unroll
        for (int nj = 0; nj < 4; nj++)
#pragma unroll
            for (int q = 0; q < 4; q++) acc[mi][nj][q] = 0.f;

    float4 pa[4], pb[2];
    // preload k-tile 0
#pragma unroll
    for (int i = 0; i < 4; i++) {
        int q = tid + 256*i; int r = q >> 3, c = (q & 7) << 2;
        pa[i] = *(const float4*)&g_A[(size_t)(m0 + r)*KP + c];
    }
#pragma unroll
    for (int i = 0; i < 2; i++) {
        int q = tid + 256*i; int r = q >> 4, c = (q & 15) << 2;
        pb[i] = *(const float4*)&X[(size_t)r*NPS + n0 + c];
    }
#pragma unroll
    for (int i = 0; i < 4; i++) {
        int q = tid + 256*i; int r = q >> 3, c = (q & 7) << 2;
        *(float4*)&Abase[r*APAD + c] = pa[i];
    }
#pragma unroll
    for (int i = 0; i < 2; i++) {
        int q = tid + 256*i; int r = q >> 4, c = (q & 15) << 2;
        *(float4*)&Bbase[r*BPAD + c] = pb[i];
    }
    __syncthreads();

    int buf = 0;
    for (int k0 = 32; k0 <= KP; k0 += 32) {
        if (k0 < KP) {
#pragma unroll
            for (int i = 0; i < 4; i++) {
                int q = tid + 256*i; int r = q >> 3, c = (q & 7) << 2;
                pa[i] = *(const float4*)&g_A[(size_t)(m0 + r)*KP + k0 + c];
            }
#pragma unroll
            for (int i = 0; i < 2; i++) {
                int q = tid + 256*i; int r = q >> 4, c = (q & 15) << 2;
                pb[i] = *(const float4*)&X[(size_t)(k0 + r)*NPS + n0 + c];
            }
        }
        const float* As = Abase + buf*ASZ;
        const float* Bs = Bbase + buf*BSZ;
#pragma unroll
        for (int ks = 0; ks < 4; ks++) {
            int kb = ks * 8;
            uint32_t af[2][4];
#pragma unroll
            for (int mi = 0; mi < 2; mi++) {
                int rb = wm*32 + mi*16;
                af[mi][0] = __float_as_uint(As[(rb + lr)*APAD + kb + lc]);
                af[mi][1] = __float_as_uint(As[(rb + 8 + lr)*APAD + kb + lc]);
                af[mi][2] = __float_as_uint(As[(rb + lr)*APAD + kb + 4 + lc]);
                af[mi][3] = __float_as_uint(As[(rb + 8 + lr)*APAD + kb + 4 + lc]);
            }
            uint32_t bf[4][2];
#pragma unroll
            for (int nj = 0; nj < 4; nj++) {
                int nb = wn*32 + nj*8;
                float b0 = Bs[(kb + lc)*BPAD + nb + lr];
                float b1 = Bs[(kb + 4 + lc)*BPAD + nb + lr];
                asm("cvt.rna.tf32.f32 %0, %1;" : "=r"(bf[nj][0]) : "f"(b0));
                asm("cvt.rna.tf32.f32 %0, %1;" : "=r"(bf[nj][1]) : "f"(b1));
            }
#pragma unroll
            for (int mi = 0; mi < 2; mi++)
#pragma unroll
                for (int nj = 0; nj < 4; nj++) {
                    asm("mma.sync.aligned.m16n8k8.row.col.f32.tf32.tf32.f32 "
                        "{%0,%1,%2,%3}, {%4,%5,%6,%7}, {%8,%9}, {%0,%1,%2,%3};"
                        : "+f"(acc[mi][nj][0]), "+f"(acc[mi][nj][1]),
                          "+f"(acc[mi][nj][2]), "+f"(acc[mi][nj][3])
                        : "r"(af[mi][0]), "r"(af[mi][1]), "r"(af[mi][2]), "r"(af[mi][3]),
                          "r"(bf[nj][0]), "r"(bf[nj][1]));
                }
        }
        if (k0 < KP) {
            int nb2 = buf ^ 1;
            float* An = Abase + nb2*ASZ;
            float* Bn = Bbase + nb2*BSZ;
#pragma unroll
            for (int i = 0; i < 4; i++) {
                int q = tid + 256*i; int r = q >> 3, c = (q & 7) << 2;
                *(float4*)&An[r*APAD + c] = pa[i];
            }
#pragma unroll
            for (int i = 0; i < 2; i++) {
                int q = tid + 256*i; int r = q >> 4, c = (q & 15) << 2;
                *(float4*)&Bn[r*BPAD + c] = pb[i];
            }
            __syncthreads();
            buf = nb2;
        }
    }

    // epilogue
#pragma unroll
    for (int mi = 0; mi < 2; mi++)
#pragma unroll
        for (int nj = 0; nj < 4; nj++) {
            int r1 = m0 + wm*32 + mi*16 + lr;
            int col = n0 + wn*32 + nj*8 + lc*2;
            *(float2*)&C[(size_t)r1*NPS + col] = make_float2(acc[mi][nj][0], acc[mi][nj][1]);
            *(float2*)&C[(size_t)(r1 + 8)*NPS + col] = make_float2(acc[mi][nj][2], acc[mi][nj][3]);
        }
}

// ---------------- gates: ru = sigmoid(cat@W0 + agg@W1 + bru); build cat2; store u ----------------
#define GATES_SMEM ((INF*DD*2 + 64*66*2) * 4)
__global__ void gates_kernel(const float* __restrict__ Wru0, const float* __restrict__ Wru1,
                             const float* __restrict__ bru) {
    extern __shared__ __align__(16) float sm[];
    float* sW0  = sm;                    // 65*128
    float* sW1  = sW0 + INF*DD;          // 65*128
    float* srow = sW1 + INF*DD;          // 64*66 (cat)
    float* sag  = srow + 64*66;          // 64*66 (agg)
    int tid = threadIdx.x;
    int r0 = blockIdx.x * 64;
    for (int i = tid; i < INF*DD; i += 512) { sW0[i] = Wru0[i]; sW1[i] = Wru1[i]; }
    for (int i = tid; i < 64*INF; i += 512) {
        int lr = i / INF, f = i % INF;
        int rid = r0 + lr, n = rid >> 4, b = rid & 15;
        srow[lr*66 + f] = g_cat[n*NPS + b*INF + f];
        sag [lr*66 + f] = g_agg[n*NPS + b*INF + f];
    }
    __syncthreads();
    int rt = tid >> 5;
    int ct = tid & 31;
    float acc[4][4];
#pragma unroll
    for (int i = 0; i < 4; i++)
#pragma unroll
        for (int j = 0; j < 4; j++) acc[i][j] = bru[ct*4 + j];
    for (int f = 0; f < INF; f++) {
        float a[4], g[4];
#pragma unroll
        for (int i = 0; i < 4; i++) {
            a[i] = srow[(rt*4+i)*66 + f];
            g[i] = sag [(rt*4+i)*66 + f];
        }
        float4 w0 = *(const float4*)&sW0[f*DD + ct*4];
        float4 w1 = *(const float4*)&sW1[f*DD + ct*4];
#pragma unroll
        for (int i = 0; i < 4; i++) {
            acc[i][0] += a[i]*w0.x + g[i]*w1.x;
            acc[i][1] += a[i]*w0.y + g[i]*w1.y;
            acc[i][2] += a[i]*w0.z + g[i]*w1.z;
            acc[i][3] += a[i]*w0.w + g[i]*w1.w;
        }
    }
#pragma unroll
    for (int i = 0; i < 4; i++) {
        int lr = rt*4 + i, rid = r0 + lr, n = rid >> 4, b = rid & 15;
#pragma unroll
        for (int j = 0; j < 4; j++) {
            int c = ct*4 + j;
            float s = 1.f / (1.f + expf(-acc[i][j]));
            if (c < HID) {
                float hv = srow[lr*66 + 1 + c];
                g_cat2[n*NPS + b*INF + 1 + c] = s * hv;
            } else {
                g_u[rid*HID + (c - HID)] = s;
            }
        }
    }
    if (tid < 64) {
        int rid = r0 + tid, n = rid >> 4, b = rid & 15;
        g_cat2[n*NPS + b*INF] = srow[tid*66];    // x column
    }
}

// ---------------- update: c = tanh(cat2@Wc0 + agg2@Wc1 + bc); h = u*h + (1-u)*c ----------------
#define UPD_SMEM ((INF*HID*2 + 64*66*2) * 4)
__global__ void update_kernel(const float* __restrict__ Wc0, const float* __restrict__ Wc1,
                              const float* __restrict__ bc) {
    extern __shared__ __align__(16) float sm[];
    float* sW0  = sm;                     // 65*64
    float* sW1  = sW0 + INF*HID;
    float* srow = sW1 + INF*HID;          // 64*66
    float* sag  = srow + 64*66;
    int tid = threadIdx.x;
    int r0 = blockIdx.x * 64;
    for (int i = tid; i < INF*HID; i += 256) { sW0[i] = Wc0[i]; sW1[i] = Wc1[i]; }
    for (int i = tid; i < 64*INF; i += 256) {
        int lr = i / INF, f = i % INF;
        int rid = r0 + lr, n = rid >> 4, b = rid & 15;
        srow[lr*66 + f] = g_cat2[n*NPS + b*INF + f];
        sag [lr*66 + f] = g_agg2[n*NPS + b*INF + f];
    }
    __syncthreads();
    int rt = tid >> 4;
    int ct = tid & 15;
    float acc[4][4];
#pragma unroll
    for (int i = 0; i < 4; i++)
#pragma unroll
        for (int j = 0; j < 4; j++) acc[i][j] = bc[ct*4 + j];
    for (int f = 0; f < INF; f++) {
        float a[4], g[4];
#pragma unroll
        for (int i = 0; i < 4; i++) {
            a[i] = srow[(rt*4+i)*66 + f];
            g[i] = sag [(rt*4+i)*66 + f];
        }
        float4 w0 = *(const float4*)&sW0[f*HID + ct*4];
        float4 w1 = *(const float4*)&sW1[f*HID + ct*4];
#pragma unroll
        for (int i = 0; i < 4; i++) {
            acc[i][0] += a[i]*w0.x + g[i]*w1.x;
            acc[i][1] += a[i]*w0.y + g[i]*w1.y;
            acc[i][2] += a[i]*w0.z + g[i]*w1.z;
            acc[i][3] += a[i]*w0.w + g[i]*w1.w;
        }
    }
#pragma unroll
    for (int i = 0; i < 4; i++) {
        int lr = rt*4 + i, rid = r0 + lr, n = rid >> 4, b = rid & 15;
#pragma unroll
        for (int j = 0; j < 4; j++) {
            int c = ct*4 + j;
            float cv = tanhf(acc[i][j]);
            float u = g_u[rid*HID + c];
            float hv = g_h[rid*HID + c];
            float hn = u*hv + (1.f - u)*cv;
            g_h[rid*HID + c] = hn;
            g_cat[n*NPS + b*INF + 1 + c] = hn;   // feed next step's cat directly
        }
    }
}

// ---------------- projection (decoder): y = h@proj_w + proj_b ----------------
__global__ void proj_kernel(const float* __restrict__ pw, const float* __restrict__ pb,
                            float* __restrict__ outp, int t) {
    int gw = (blockIdx.x * blockDim.x + threadIdx.x) >> 5;
    int lane = threadIdx.x & 31;
    if (gw >= BB*NN) return;
    int rid = gw;                        // rid = n*16+b
    float s = g_h[rid*HID + lane]*pw[lane] + g_h[rid*HID + 32 + lane]*pw[32 + lane];
#pragma unroll
    for (int off = 16; off > 0; off >>= 1) s += __shfl_down_sync(0xffffffffu, s, off);
    if (lane == 0) {
        int n = rid >> 4, b = rid & 15;
        float y = s + pb[0];
        g_yprev[b*NN + n] = y;
        outp[(b*HH + t)*NN + n] = y;
    }
}

// ---------------- loss: mean((outputs-targets)^2), single block deterministic ----------------
__global__ void loss_kernel(const float* __restrict__ outp, const float* __restrict__ targ,
                            float* __restrict__ lossout) {
    __shared__ double sred[256];
    int tid = threadIdx.x;
    double s = 0.0;
    for (int i = tid; i < BB*HH*NN; i += 256) {
        float d = outp[i] - targ[i];
        s += (double)d * (double)d;
    }
    sred[tid] = s;
    __syncthreads();
    for (int off = 128; off > 0; off >>= 1) {
        if (tid < off) sred[tid] += sred[tid+off];
        __syncthreads();
    }
    if (tid == 0) lossout[0] = (float)(sred[0] / (double)(BB*HH*NN));
}

// ---------------- host ----------------
extern "C" void kernel_launch(void* const* d_in, const int* in_sizes, int n_in,
                              void* d_out, int out_size) {
    const float* inputs  = (const float*)d_in[0];
    const float* entire  = (const float*)d_in[1];
    const float* targets = (const float*)d_in[2];
    const float* unoise  = (const float*)d_in[3];
    const float* c1w = (const float*)d_in[4];
    const float* c1b = (const float*)d_in[5];
    const float* c2w = (const float*)d_in[6];
    const float* c2b = (const float*)d_in[7];
    const float* fcw = (const float*)d_in[8];
    const float* fcb = (const float*)d_in[9];
    const float* Wa  = (const float*)d_in[10];
    const float* Wb  = (const float*)d_in[11];
    const float* b1  = (const float*)d_in[12];
    const float* W2  = (const float*)d_in[13];
    const float* b2  = (const float*)d_in[14];
    const float* eWru0 = (const float*)d_in[15];
    const float* eWru1 = (const float*)d_in[16];
    const float* ebru  = (const float*)d_in[17];
    const float* eWc0  = (const float*)d_in[18];
    const float* eWc1  = (const float*)d_in[19];
    const float* ebc   = (const float*)d_in[20];
    const float* dWru0 = (const float*)d_in[21];
    const float* dWru1 = (const float*)d_in[22];
    const float* dbru  = (const float*)d_in[23];
    const float* dWc0  = (const float*)d_in[24];
    const float* dWc1  = (const float*)d_in[25];
    const float* dbc   = (const float*)d_in[26];
    const float* pw    = (const float*)d_in[27];
    const float* pb    = (const float*)d_in[28];

    float* out      = (float*)d_out;
    float* maskout  = out;                       // N*N
    float* outputs  = out + NN*NN;               // B*H*N
    float* lossout  = out + NN*NN + BB*HH*NN;    // 1

    cudaFuncSetAttribute(gates_kernel,  cudaFuncAttributeMaxDynamicSharedMemorySize, GATES_SMEM);
    cudaFuncSetAttribute(update_kernel, cudaFuncAttributeMaxDynamicSharedMemorySize, UPD_SMEM);
    cudaFuncSetAttribute(mma_gemm_kernel, cudaFuncAttributeMaxDynamicSharedMemorySize, MMA_SMEM);

    init_kernel<<<(KP*NPS + 255)/256, 256>>>();
    conv_pool_kernel<<<NN, 256>>>(entire, c1w, c1b, c2w, c2b);
    fc_fab_kernel<<<NN, DD>>>(fcw, fcb, Wa, Wb);
    dim3 eg(63, 63);
    edge_kernel<<<eg, 256>>>(b1, W2, b2, unoise, maskout);
    rownorm_kernel<<<NN, 256>>>(maskout);

    dim3 gg(NPS/64, MP/128);   // (17, 8) = 136 blocks
    int sx_blocks = (NN*BB + 255)/256;

    // encoder
    for (int s = 0; s < SS; s++) {
        set_x_kernel<<<sx_blocks, 256>>>(inputs + s*NN, SS*NN, 0);
        mma_gemm_kernel<<<gg, 256, MMA_SMEM>>>(0);
        gates_kernel<<<BB*NN/64, 512, GATES_SMEM>>>(eWru0, eWru1, ebru);
        mma_gemm_kernel<<<gg, 256, MMA_SMEM>>>(1);
        update_kernel<<<BB*NN/64, 256, UPD_SMEM>>>(eWc0, eWc1, ebc);
    }
    // decoder
    for (int t = 0; t < HH; t++) {
        set_x_kernel<<<sx_blocks, 256>>>(inputs, NN, 1);   // x from g_yprev
        mma_gemm_kernel<<<gg, 256, MMA_SMEM>>>(0);
        gates_kernel<<<BB*NN/64, 512, GATES_SMEM>>>(dWru0, dWru1, dbru);
        mma_gemm_kernel<<<gg, 256, MMA_SMEM>>>(1);
        update_kernel<<<BB*NN/64, 256, UPD_SMEM>>>(dWc0, dWc1, dbc);
        proj_kernel<<<(BB*NN*32 + 255)/256, 256>>>(pw, pb, outputs, t);
    }
    loss_kernel<<<1, 256>>>(outputs, targets, lossout);
}

// round 14
// speedup vs baseline: 1.2498x; 1.0036x over previous
#include <cuda_runtime.h>
#include <math.h>
#include <stdint.h>

// ---------------- problem dims ----------------
#define NN 1000
#define TT 4000
#define BB 16
#define SS 12
#define HH 12
#define C1C 8
#define C2C 16
#define KW 10
#define DD 128
#define HID 64
#define INF 65           // 1 + HID
#define T1L (TT-KW+1)    // 3991
#define T2L (T1L-KW+1)   // 3982

// padded GEMM dims (zero-pad regions are never written -> stay 0)
#define MP 1024
#define KP 1024
#define NPS 1088         // padded column stride (17 * 64)

// ---------------- scratch (device globals; no allocation allowed) ----------------
__device__ __align__(16) float g_A[MP*KP];
__device__ __align__(16) float g_cat[KP*NPS];
__device__ __align__(16) float g_cat2[KP*NPS];
__device__ __align__(16) float g_agg[MP*NPS];
__device__ __align__(16) float g_agg2[MP*NPS];
__device__ __align__(16) float g_h[BB*NN*HID];     // layout: rid = n*16+b, [rid][HID]
__device__ __align__(16) float g_u[BB*NN*HID];     // same layout
__device__ __align__(16) float g_yprev[BB*NN];     // [b*NN+n]
__device__ __align__(16) float g_pooled[NN*C2C];
__device__ __align__(16) float g_fa[NN*DD];
__device__ __align__(16) float g_fb[NN*DD];

// ---------------- init: zero h / yprev / cat each run (graph-replay determinism) ----------------
__global__ void init_kernel() {
    int i = blockIdx.x * blockDim.x + threadIdx.x;
    if (i < KP*NPS) g_cat[i] = 0.f;
    if (i < BB*NN*HID) g_h[i] = 0.f;
    if (i < BB*NN) g_yprev[i] = 0.f;
}

// ---------------- fused conv1+relu+conv2+relu+meanpool, one block per node ----------------
#define CT 512
__global__ void conv_pool_kernel(const float* __restrict__ x,
                                 const float* __restrict__ w1, const float* __restrict__ b1,
                                 const float* __restrict__ w2, const float* __restrict__ b2) {
    int n = blockIdx.x;
    const float* xs = x + n*TT;
    __shared__ float sw1[C1C*KW];
    __shared__ float sw2[C2C*C1C*KW];
    __shared__ float sb1[C1C], sb2[C2C];
    __shared__ float sx[CT + 2*(KW-1)];
    __shared__ float sc1[C1C][CT + KW - 1];
    int tid = threadIdx.x;
    if (tid < C1C*KW) sw1[tid] = w1[tid];
    for (int i = tid; i < C2C*C1C*KW; i += 256) sw2[i] = w2[i];
    if (tid < C1C) sb1[tid] = b1[tid];
    if (tid < C2C) sb2[tid] = b2[tid];

    float tacc[C2C];
#pragma unroll
    for (int c = 0; c < C2C; c++) tacc[c] = 0.f;

    for (int t0 = 0; t0 < T2L; t0 += CT) {
        int cnt = min(CT, T2L - t0);
        __syncthreads();
        for (int i = tid; i < cnt + 2*(KW-1); i += 256) sx[i] = xs[t0 + i];
        __syncthreads();
        for (int p = tid; p < cnt + KW - 1; p += 256) {
#pragma unroll
            for (int c = 0; c < C1C; c++) {
                float s = sb1[c];
#pragma unroll
                for (int k = 0; k < KW; k++) s += sx[p+k] * sw1[c*KW+k];
                sc1[c][p] = fmaxf(s, 0.f);
            }
        }
        __syncthreads();
        for (int q = tid; q < cnt; q += 256) {
            float acc[C2C];
#pragma unroll
            for (int c = 0; c < C2C; c++) acc[c] = sb2[c];
#pragma unroll
            for (int ci = 0; ci < C1C; ci++) {
#pragma unroll
                for (int k = 0; k < KW; k++) {
                    float v = sc1[ci][q+k];
#pragma unroll
                    for (int c = 0; c < C2C; c++) acc[c] += v * sw2[(c*C1C+ci)*KW + k];
                }
            }
#pragma unroll
            for (int c = 0; c < C2C; c++) tacc[c] += fmaxf(acc[c], 0.f);
        }
    }
    __shared__ float sred[256];
    for (int c = 0; c < C2C; c++) {
        __syncthreads();
        sred[tid] = tacc[c];
        __syncthreads();
        for (int off = 128; off > 0; off >>= 1) {
            if (tid < off) sred[tid] += sred[tid+off];
            __syncthreads();
        }
        if (tid == 0) g_pooled[n*C2C + c] = sred[0] / (float)T2L;
    }
}

// ---------------- fc + fa/fb, one block (128 thr) per node ----------------
__global__ void fc_fab_kernel(const float* __restrict__ fcw, const float* __restrict__ fcb,
                              const float* __restrict__ Wa, const float* __restrict__ Wb) {
    int n = blockIdx.x;
    int d = threadIdx.x;
    __shared__ float sp[C2C];
    __shared__ float sf[DD];
    if (d < C2C) sp[d] = g_pooled[n*C2C + d];
    __syncthreads();
    float v = fcb[d];
#pragma unroll
    for (int c = 0; c < C2C; c++) v += sp[c] * fcw[c*DD + d];
    sf[d] = fmaxf(v, 0.f);
    __syncthreads();
    float a = 0.f, b = 0.f;
    for (int k = 0; k < DD; k++) {
        float fv = sf[k];
        a += fv * Wa[k*DD + d];
        b += fv * Wb[k*DD + d];
    }
    g_fa[n*DD + d] = a;
    g_fb[n*DD + d] = b;
}

// ---------------- edge MLP + gumbel hard mask ----------------
__global__ void edge_kernel(const float* __restrict__ b1v, const float* __restrict__ W2,
                            const float* __restrict__ b2v, const float* __restrict__ unoise,
                            float* __restrict__ mask) {
    __shared__ float sfa[16][DD+1], sfb[16][DD+1];
    __shared__ float sb1[DD], sw2[2*DD];
    int tid = threadIdx.x;
    int i0 = blockIdx.y * 16, j0 = blockIdx.x * 16;
    for (int idx = tid; idx < 16*DD; idx += 256) {
        int r = idx >> 7, c = idx & 127;
        sfa[r][c] = (i0 + r < NN) ? g_fa[(i0+r)*DD + c] : 0.f;
        sfb[r][c] = (j0 + r < NN) ? g_fb[(j0+r)*DD + c] : 0.f;
    }
    if (tid < DD) sb1[tid] = b1v[tid];
    if (tid < 2*DD) sw2[tid] = W2[tid];
    __syncthreads();
    int ti = tid >> 4, tj = tid & 15;
    int i = i0 + ti, j = j0 + tj;
    if (i < NN && j < NN) {
        float a0 = b2v[0], a1 = b2v[1];
#pragma unroll 4
        for (int k = 0; k < DD; k++) {
            float v = fmaxf(sfa[ti][k] + sfb[tj][k] + sb1[k], 0.f);
            a0 += v * sw2[2*k];
            a1 += v * sw2[2*k+1];
        }
        int e = i*NN + j;
        float u0 = unoise[2*e], u1 = unoise[2*e+1];
        float g0 = -logf(-logf(u0 + 1e-10f) + 1e-10f);
        float g1 = -logf(-logf(u1 + 1e-10f) + 1e-10f);
        float m = ((a0 + g0) >= (a1 + g1)) ? 1.f : 0.f;
        if (i == j) m = 0.f;
        mask[e] = m;
    }
}

// ---------------- row-normalize mask -> A (padded layout, pre-rounded to tf32) ----------------
__global__ void rownorm_kernel(const float* __restrict__ mask) {
    int i = blockIdx.x;
    int tid = threadIdx.x;
    __shared__ float sred[256];
    float s = 0.f;
    for (int j = tid; j < NN; j += 256) s += mask[i*NN + j];
    sred[tid] = s;
    __syncthreads();
    for (int off = 128; off > 0; off >>= 1) {
        if (tid < off) sred[tid] += sred[tid+off];
        __syncthreads();
    }
    float inv = 1.f / (sred[0] + 1e-6f);
    for (int j = tid; j < NN; j += 256) {
        float v = mask[i*NN + j] * inv;
        uint32_t t;
        asm("cvt.rna.tf32.f32 %0, %1;" : "=r"(t) : "f"(v));
        g_A[i*KP + j] = __uint_as_float(t);
    }
}

// ---------------- set x column of g_cat ----------------
__global__ void set_x_kernel(const float* __restrict__ x, int bstride, int use_yprev) {
    int idx = blockIdx.x * blockDim.x + threadIdx.x;
    if (idx >= NN*BB) return;
    int n = idx >> 4, b = idx & 15;
    float v = use_yprev ? g_yprev[b*NN + n] : x[b*bstride + n];
    g_cat[n*NPS + b*INF] = v;
}

// ---------------- tf32 tensor-core GEMM: C[MP,NPS] = A * X ----------------
// CTA tile 128x64, 8 warps as 4(m) x 2(n), warp tile 32x32, mma.m16n8k8.tf32
#define APAD 36
#define BPAD 72
#define ASZ (128*APAD)
#define BSZ (32*BPAD)
#define MMA_SMEM ((2*ASZ + 2*BSZ) * 4)
__global__ void __launch_bounds__(256) mma_gemm_kernel(int which) {
    const float* __restrict__ X = which ? g_cat2 : g_cat;
    float* __restrict__ C = which ? g_agg2 : g_agg;
    extern __shared__ __align__(16) float sm[];
    float* Abase = sm;                 // 2 x [128][APAD]
    float* Bbase = sm + 2*ASZ;         // 2 x [32][BPAD]

    int tid  = threadIdx.x;
    int lane = tid & 31;
    int wid  = tid >> 5;
    int wm = wid >> 1;                 // 0..3
    int wn = wid & 1;                  // 0..1
    int lr = lane >> 2;                // 0..7
    int lc = lane & 3;                 // 0..3
    int m0 = blockIdx.y * 128, n0 = blockIdx.x * 64;

    float acc[2][4][4];
#pragma unroll
    for (int mi = 0; mi < 2; mi++)
#pragma unroll
        for (int nj = 0; nj < 4; nj++)
#pragma unroll
            for (int q = 0; q < 4; q++) acc[mi][nj][q] = 0.f;

    float4 pa[4], pb[2];
    // preload k-tile 0
#pragma unroll
    for (int i = 0; i < 4; i++) {
        int q = tid + 256*i; int r = q >> 3, c = (q & 7) << 2;
        pa[i] = *(const float4*)&g_A[(size_t)(m0 + r)*KP + c];
    }
#pragma unroll
    for (int i = 0; i < 2; i++) {
        int q = tid + 256*i; int r = q >> 4, c = (q & 15) << 2;
        pb[i] = *(const float4*)&X[(size_t)r*NPS + n0 + c];
    }
#pragma unroll
    for (int i = 0; i < 4; i++) {
        int q = tid + 256*i; int r = q >> 3, c = (q & 7) << 2;
        *(float4*)&Abase[r*APAD + c] = pa[i];
    }
#pragma unroll
    for (int i = 0; i < 2; i++) {
        int q = tid + 256*i; int r = q >> 4, c = (q & 15) << 2;
        *(float4*)&Bbase[r*BPAD + c] = pb[i];
    }
    __syncthreads();

    int buf = 0;
    for (int k0 = 32; k0 <= KP; k0 += 32) {
        if (k0 < KP) {
#pragma unroll
            for (int i = 0; i < 4; i++) {
                int q = tid + 256*i; int r = q >> 3, c = (q & 7) << 2;
                pa[i] = *(const float4*)&g_A[(size_t)(m0 + r)*KP + k0 + c];
            }
#pragma unroll
            for (int i = 0; i < 2; i++) {
                int q = tid + 256*i; int r = q >> 4, c = (q & 15) << 2;
                pb[i] = *(const float4*)&X[(size_t)(k0 + r)*NPS + n0 + c];
            }
        }
        const float* As = Abase + buf*ASZ;
        const float* Bs = Bbase + buf*BSZ;
#pragma unroll
        for (int ks = 0; ks < 4; ks++) {
            int kb = ks * 8;
            uint32_t af[2][4];
#pragma unroll
            for (int mi = 0; mi < 2; mi++) {
                int rb = wm*32 + mi*16;
                af[mi][0] = __float_as_uint(As[(rb + lr)*APAD + kb + lc]);
                af[mi][1] = __float_as_uint(As[(rb + 8 + lr)*APAD + kb + lc]);
                af[mi][2] = __float_as_uint(As[(rb + lr)*APAD + kb + 4 + lc]);
                af[mi][3] = __float_as_uint(As[(rb + 8 + lr)*APAD + kb + 4 + lc]);
            }
            uint32_t bf[4][2];
#pragma unroll
            for (int nj = 0; nj < 4; nj++) {
                int nb = wn*32 + nj*8;
                float b0 = Bs[(kb + lc)*BPAD + nb + lr];
                float b1 = Bs[(kb + 4 + lc)*BPAD + nb + lr];
                asm("cvt.rna.tf32.f32 %0, %1;" : "=r"(bf[nj][0]) : "f"(b0));
                asm("cvt.rna.tf32.f32 %0, %1;" : "=r"(bf[nj][1]) : "f"(b1));
            }
#pragma unroll
            for (int mi = 0; mi < 2; mi++)
#pragma unroll
                for (int nj = 0; nj < 4; nj++) {
                    asm("mma.sync.aligned.m16n8k8.row.col.f32.tf32.tf32.f32 "
                        "{%0,%1,%2,%3}, {%4,%5,%6,%7}, {%8,%9}, {%0,%1,%2,%3};"
                        : "+f"(acc[mi][nj][0]), "+f"(acc[mi][nj][1]),
                          "+f"(acc[mi][nj][2]), "+f"(acc[mi][nj][3])
                        : "r"(af[mi][0]), "r"(af[mi][1]), "r"(af[mi][2]), "r"(af[mi][3]),
                          "r"(bf[nj][0]), "r"(bf[nj][1]));
                }
        }
        if (k0 < KP) {
            int nb2 = buf ^ 1;
            float* An = Abase + nb2*ASZ;
            float* Bn = Bbase + nb2*BSZ;
#pragma unroll
            for (int i = 0; i < 4; i++) {
                int q = tid + 256*i; int r = q >> 3, c = (q & 7) << 2;
                *(float4*)&An[r*APAD + c] = pa[i];
            }
#pragma unroll
            for (int i = 0; i < 2; i++) {
                int q = tid + 256*i; int r = q >> 4, c = (q & 15) << 2;
                *(float4*)&Bn[r*BPAD + c] = pb[i];
            }
            __syncthreads();
            buf = nb2;
        }
    }

    // epilogue
#pragma unroll
    for (int mi = 0; mi < 2; mi++)
#pragma unroll
        for (int nj = 0; nj < 4; nj++) {
            int r1 = m0 + wm*32 + mi*16 + lr;
            int col = n0 + wn*32 + nj*8 + lc*2;
            *(float2*)&C[(size_t)r1*NPS + col] = make_float2(acc[mi][nj][0], acc[mi][nj][1]);
            *(float2*)&C[(size_t)(r1 + 8)*NPS + col] = make_float2(acc[mi][nj][2], acc[mi][nj][3]);
        }
}

// ---------------- gates: ru = sigmoid(cat@W0 + agg@W1 + bru); build cat2; store u ----------------
#define GATES_SMEM ((INF*DD*2 + 64*66*2) * 4)
__global__ void gates_kernel(const float* __restrict__ Wru0, const float* __restrict__ Wru1,
                             const float* __restrict__ bru) {
    extern __shared__ __align__(16) float sm[];
    float* sW0  = sm;                    // 65*128
    float* sW1  = sW0 + INF*DD;          // 65*128
    float* srow = sW1 + INF*DD;          // 64*66 (cat)
    float* sag  = srow + 64*66;          // 64*66 (agg)
    int tid = threadIdx.x;
    int r0 = blockIdx.x * 64;
    for (int i = tid; i < INF*DD; i += 512) { sW0[i] = Wru0[i]; sW1[i] = Wru1[i]; }
    for (int i = tid; i < 64*INF; i += 512) {
        int lr = i / INF, f = i % INF;
        int rid = r0 + lr, n = rid >> 4, b = rid & 15;
        srow[lr*66 + f] = g_cat[n*NPS + b*INF + f];
        sag [lr*66 + f] = g_agg[n*NPS + b*INF + f];
    }
    __syncthreads();
    int rt = tid >> 5;
    int ct = tid & 31;
    float acc[4][4];
#pragma unroll
    for (int i = 0; i < 4; i++)
#pragma unroll
        for (int j = 0; j < 4; j++) acc[i][j] = bru[ct*4 + j];
    for (int f = 0; f < INF; f++) {
        float a[4], g[4];
#pragma unroll
        for (int i = 0; i < 4; i++) {
            a[i] = srow[(rt*4+i)*66 + f];
            g[i] = sag [(rt*4+i)*66 + f];
        }
        float4 w0 = *(const float4*)&sW0[f*DD + ct*4];
        float4 w1 = *(const float4*)&sW1[f*DD + ct*4];
#pragma unroll
        for (int i = 0; i < 4; i++) {
            acc[i][0] += a[i]*w0.x + g[i]*w1.x;
            acc[i][1] += a[i]*w0.y + g[i]*w1.y;
            acc[i][2] += a[i]*w0.z + g[i]*w1.z;
            acc[i][3] += a[i]*w0.w + g[i]*w1.w;
        }
    }
#pragma unroll
    for (int i = 0; i < 4; i++) {
        int lr = rt*4 + i, rid = r0 + lr, n = rid >> 4, b = rid & 15;
#pragma unroll
        for (int j = 0; j < 4; j++) {
            int c = ct*4 + j;
            float s = 1.f / (1.f + expf(-acc[i][j]));
            if (c < HID) {
                float hv = srow[lr*66 + 1 + c];
                g_cat2[n*NPS + b*INF + 1 + c] = s * hv;
            } else {
                g_u[rid*HID + (c - HID)] = s;
            }
        }
    }
    if (tid < 64) {
        int rid = r0 + tid, n = rid >> 4, b = rid & 15;
        g_cat2[n*NPS + b*INF] = srow[tid*66];    // x column
    }
}

// ---------------- update: c = tanh(cat2@Wc0 + agg2@Wc1 + bc); h = u*h + (1-u)*c ----------------
#define UPD_SMEM ((INF*HID*2 + 64*66*2) * 4)
__global__ void update_kernel(const float* __restrict__ Wc0, const float* __restrict__ Wc1,
                              const float* __restrict__ bc) {
    extern __shared__ __align__(16) float sm[];
    float* sW0  = sm;                     // 65*64
    float* sW1  = sW0 + INF*HID;
    float* srow = sW1 + INF*HID;          // 64*66
    float* sag  = srow + 64*66;
    int tid = threadIdx.x;
    int r0 = blockIdx.x * 64;
    for (int i = tid; i < INF*HID; i += 256) { sW0[i] = Wc0[i]; sW1[i] = Wc1[i]; }
    for (int i = tid; i < 64*INF; i += 256) {
        int lr = i / INF, f = i % INF;
        int rid = r0 + lr, n = rid >> 4, b = rid & 15;
        srow[lr*66 + f] = g_cat2[n*NPS + b*INF + f];
        sag [lr*66 + f] = g_agg2[n*NPS + b*INF + f];
    }
    __syncthreads();
    int rt = tid >> 4;
    int ct = tid & 15;
    float acc[4][4];
#pragma unroll
    for (int i = 0; i < 4; i++)
#pragma unroll
        for (int j = 0; j < 4; j++) acc[i][j] = bc[ct*4 + j];
    for (int f = 0; f < INF; f++) {
        float a[4], g[4];
#pragma unroll
        for (int i = 0; i < 4; i++) {
            a[i] = srow[(rt*4+i)*66 + f];
            g[i] = sag [(rt*4+i)*66 + f];
        }
        float4 w0 = *(const float4*)&sW0[f*HID + ct*4];
        float4 w1 = *(const float4*)&sW1[f*HID + ct*4];
#pragma unroll
        for (int i = 0; i < 4; i++) {
            acc[i][0] += a[i]*w0.x + g[i]*w1.x;
            acc[i][1] += a[i]*w0.y + g[i]*w1.y;
            acc[i][2] += a[i]*w0.z + g[i]*w1.z;
            acc[i][3] += a[i]*w0.w + g[i]*w1.w;
        }
    }
#pragma unroll
    for (int i = 0; i < 4; i++) {
        int lr = rt*4 + i, rid = r0 + lr, n = rid >> 4, b = rid & 15;
#pragma unroll
        for (int j = 0; j < 4; j++) {
            int c = ct*4 + j;
            float cv = tanhf(acc[i][j]);
            float u = g_u[rid*HID + c];
            float hv = g_h[rid*HID + c];
            float hn = u*hv + (1.f - u)*cv;
            g_h[rid*HID + c] = hn;
            g_cat[n*NPS + b*INF + 1 + c] = hn;   // feed next step's cat directly
        }
    }
}

// ---------------- projection (decoder): y = h@proj_w + proj_b ----------------
__global__ void proj_kernel(const float* __restrict__ pw, const float* __restrict__ pb,
                            float* __restrict__ outp, int t) {
    int gw = (blockIdx.x * blockDim.x + threadIdx.x) >> 5;
    int lane = threadIdx.x & 31;
    if (gw >= BB*NN) return;
    int rid = gw;                        // rid = n*16+b
    float s = g_h[rid*HID + lane]*pw[lane] + g_h[rid*HID + 32 + lane]*pw[32 + lane];
#pragma unroll
    for (int off = 16; off > 0; off >>= 1) s += __shfl_down_sync(0xffffffffu, s, off);
    if (lane == 0) {
        int n = rid >> 4, b = rid & 15;
        float y = s + pb[0];
        g_yprev[b*NN + n] = y;
        outp[(b*HH + t)*NN + n] = y;
    }
}

// ---------------- loss: mean((outputs-targets)^2), single block deterministic ----------------
__global__ void loss_kernel(const float* __restrict__ outp, const float* __restrict__ targ,
                            float* __restrict__ lossout) {
    __shared__ double sred[256];
    int tid = threadIdx.x;
    double s = 0.0;
    for (int i = tid; i < BB*HH*NN; i += 256) {
        float d = outp[i] - targ[i];
        s += (double)d * (double)d;
    }
    sred[tid] = s;
    __syncthreads();
    for (int off = 128; off > 0; off >>= 1) {
        if (tid < off) sred[tid] += sred[tid+off];
        __syncthreads();
    }
    if (tid == 0) lossout[0] = (float)(sred[0] / (double)(BB*HH*NN));
}

// ---------------- host ----------------
extern "C" void kernel_launch(void* const* d_in, const int* in_sizes, int n_in,
                              void* d_out, int out_size) {
    const float* inputs  = (const float*)d_in[0];
    const float* entire  = (const float*)d_in[1];
    const float* targets = (const float*)d_in[2];
    const float* unoise  = (const float*)d_in[3];
    const float* c1w = (const float*)d_in[4];
    const float* c1b = (const float*)d_in[5];
    const float* c2w = (const float*)d_in[6];
    const float* c2b = (const float*)d_in[7];
    const float* fcw = (const float*)d_in[8];
    const float* fcb = (const float*)d_in[9];
    const float* Wa  = (const float*)d_in[10];
    const float* Wb  = (const float*)d_in[11];
    const float* b1  = (const float*)d_in[12];
    const float* W2  = (const float*)d_in[13];
    const float* b2  = (const float*)d_in[14];
    const float* eWru0 = (const float*)d_in[15];
    const float* eWru1 = (const float*)d_in[16];
    const float* ebru  = (const float*)d_in[17];
    const float* eWc0  = (const float*)d_in[18];
    const float* eWc1  = (const float*)d_in[19];
    const float* ebc   = (const float*)d_in[20];
    const float* dWru0 = (const float*)d_in[21];
    const float* dWru1 = (const float*)d_in[22];
    const float* dbru  = (const float*)d_in[23];
    const float* dWc0  = (const float*)d_in[24];
    const float* dWc1  = (const float*)d_in[25];
    const float* dbc   = (const float*)d_in[26];
    const float* pw    = (const float*)d_in[27];
    const float* pb    = (const float*)d_in[28];

    float* out      = (float*)d_out;
    float* maskout  = out;                       // N*N
    float* outputs  = out + NN*NN;               // B*H*N
    float* lossout  = out + NN*NN + BB*HH*NN;    // 1

    cudaFuncSetAttribute(gates_kernel,  cudaFuncAttributeMaxDynamicSharedMemorySize, GATES_SMEM);
    cudaFuncSetAttribute(update_kernel, cudaFuncAttributeMaxDynamicSharedMemorySize, UPD_SMEM);
    cudaFuncSetAttribute(mma_gemm_kernel, cudaFuncAttributeMaxDynamicSharedMemorySize, MMA_SMEM);

    init_kernel<<<(KP*NPS + 255)/256, 256>>>();
    conv_pool_kernel<<<NN, 256>>>(entire, c1w, c1b, c2w, c2b);
    fc_fab_kernel<<<NN, DD>>>(fcw, fcb, Wa, Wb);
    dim3 eg(63, 63);
    edge_kernel<<<eg, 256>>>(b1, W2, b2, unoise, maskout);
    rownorm_kernel<<<NN, 256>>>(maskout);

    dim3 gg(NPS/64, MP/128);   // (17, 8) = 136 blocks
    int sx_blocks = (NN*BB + 255)/256;

    // encoder
    for (int s = 0; s < SS; s++) {
        set_x_kernel<<<sx_blocks, 256>>>(inputs + s*NN, SS*NN, 0);
        mma_gemm_kernel<<<gg, 256, MMA_SMEM>>>(0);
        gates_kernel<<<BB*NN/64, 512, GATES_SMEM>>>(eWru0, eWru1, ebru);
        mma_gemm_kernel<<<gg, 256, MMA_SMEM>>>(1);
        update_kernel<<<BB*NN/64, 256, UPD_SMEM>>>(eWc0, eWc1, ebc);
    }
    // decoder
    for (int t = 0; t < HH; t++) {
        set_x_kernel<<<sx_blocks, 256>>>(inputs, NN, 1);   // x from g_yprev
        mma_gemm_kernel<<<gg, 256, MMA_SMEM>>>(0);
        gates_kernel<<<BB*NN/64, 512, GATES_SMEM>>>(dWru0, dWru1, dbru);
        mma_gemm_kernel<<<gg, 256, MMA_SMEM>>>(1);
        update_kernel<<<BB*NN/64, 256, UPD_SMEM>>>(dWc0, dWc1, dbc);
        proj_kernel<<<(BB*NN*32 + 255)/256, 256>>>(pw, pb, outputs, t);
    }
    loss_kernel<<<1, 256>>>(outputs, targets, lossout);
}

// round 16
// speedup vs baseline: 1.2635x; 1.0110x over previous
#include <cuda_runtime.h>
#include <math.h>
#include <stdint.h>

// ---------------- problem dims ----------------
#define NN 1000
#define TT 4000
#define BB 16
#define SS 12
#define HH 12
#define C1C 8
#define C2C 16
#define KW 10
#define DD 128
#define HID 64
#define INF 65           // 1 + HID
#define T1L (TT-KW+1)    // 3991
#define T2L (T1L-KW+1)   // 3982

// padded GEMM dims (zero-pad regions are never written -> stay 0)
#define MP 1024
#define KP 1024
#define NPS 1088         // padded column stride (17 * 64)

// ---------------- scratch (device globals; no allocation allowed) ----------------
__device__ __align__(16) float g_A[MP*KP];
__device__ __align__(16) float g_cat[KP*NPS];
__device__ __align__(16) float g_cat2[KP*NPS];
__device__ __align__(16) float g_agg[MP*NPS];
__device__ __align__(16) float g_agg2[MP*NPS];
__device__ __align__(16) float g_h[BB*NN*HID];     // layout: rid = n*16+b, [rid][HID]
__device__ __align__(16) float g_u[BB*NN*HID];     // same layout
__device__ __align__(16) float g_yprev[BB*NN];     // [b*NN+n]
__device__ __align__(16) float g_pooled[NN*C2C];
__device__ __align__(16) float g_fa[NN*DD];
__device__ __align__(16) float g_fb[NN*DD];

// ---------------- init: zero h / yprev / cat each run (graph-replay determinism) ----------------
__global__ void init_kernel() {
    int i = blockIdx.x * blockDim.x + threadIdx.x;
    if (i < KP*NPS) g_cat[i] = 0.f;
    if (i < BB*NN*HID) g_h[i] = 0.f;
    if (i < BB*NN) g_yprev[i] = 0.f;
}

// ---------------- fused conv1+relu+conv2+relu+meanpool, one block per node ----------------
#define CT 512
__global__ void conv_pool_kernel(const float* __restrict__ x,
                                 const float* __restrict__ w1, const float* __restrict__ b1,
                                 const float* __restrict__ w2, const float* __restrict__ b2) {
    int n = blockIdx.x;
    const float* xs = x + n*TT;
    __shared__ float sw1[C1C*KW];
    __shared__ float sw2[C2C*C1C*KW];
    __shared__ float sb1[C1C], sb2[C2C];
    __shared__ float sx[CT + 2*(KW-1)];
    __shared__ float sc1[C1C][CT + KW - 1];
    int tid = threadIdx.x;
    if (tid < C1C*KW) sw1[tid] = w1[tid];
    for (int i = tid; i < C2C*C1C*KW; i += 256) sw2[i] = w2[i];
    if (tid < C1C) sb1[tid] = b1[tid];
    if (tid < C2C) sb2[tid] = b2[tid];

    float tacc[C2C];
#pragma unroll
    for (int c = 0; c < C2C; c++) tacc[c] = 0.f;

    for (int t0 = 0; t0 < T2L; t0 += CT) {
        int cnt = min(CT, T2L - t0);
        __syncthreads();
        for (int i = tid; i < cnt + 2*(KW-1); i += 256) sx[i] = xs[t0 + i];
        __syncthreads();
        for (int p = tid; p < cnt + KW - 1; p += 256) {
#pragma unroll
            for (int c = 0; c < C1C; c++) {
                float s = sb1[c];
#pragma unroll
                for (int k = 0; k < KW; k++) s += sx[p+k] * sw1[c*KW+k];
                sc1[c][p] = fmaxf(s, 0.f);
            }
        }
        __syncthreads();
        for (int q = tid; q < cnt; q += 256) {
            float acc[C2C];
#pragma unroll
            for (int c = 0; c < C2C; c++) acc[c] = sb2[c];
#pragma unroll
            for (int ci = 0; ci < C1C; ci++) {
#pragma unroll
                for (int k = 0; k < KW; k++) {
                    float v = sc1[ci][q+k];
#pragma unroll
                    for (int c = 0; c < C2C; c++) acc[c] += v * sw2[(c*C1C+ci)*KW + k];
                }
            }
#pragma unroll
            for (int c = 0; c < C2C; c++) tacc[c] += fmaxf(acc[c], 0.f);
        }
    }
    __shared__ float sred[256];
    for (int c = 0; c < C2C; c++) {
        __syncthreads();
        sred[tid] = tacc[c];
        __syncthreads();
        for (int off = 128; off > 0; off >>= 1) {
            if (tid < off) sred[tid] += sred[tid+off];
            __syncthreads();
        }
        if (tid == 0) g_pooled[n*C2C + c] = sred[0] / (float)T2L;
    }
}

// ---------------- fc + fa/fb, one block (128 thr) per node ----------------
__global__ void fc_fab_kernel(const float* __restrict__ fcw, const float* __restrict__ fcb,
                              const float* __restrict__ Wa, const float* __restrict__ Wb) {
    int n = blockIdx.x;
    int d = threadIdx.x;
    __shared__ float sp[C2C];
    __shared__ float sf[DD];
    if (d < C2C) sp[d] = g_pooled[n*C2C + d];
    __syncthreads();
    float v = fcb[d];
#pragma unroll
    for (int c = 0; c < C2C; c++) v += sp[c] * fcw[c*DD + d];
    sf[d] = fmaxf(v, 0.f);
    __syncthreads();
    float a = 0.f, b = 0.f;
    for (int k = 0; k < DD; k++) {
        float fv = sf[k];
        a += fv * Wa[k*DD + d];
        b += fv * Wb[k*DD + d];
    }
    g_fa[n*DD + d] = a;
    g_fb[n*DD + d] = b;
}

// ---------------- edge MLP + gumbel hard mask ----------------
__global__ void edge_kernel(const float* __restrict__ b1v, const float* __restrict__ W2,
                            const float* __restrict__ b2v, const float* __restrict__ unoise,
                            float* __restrict__ mask) {
    __shared__ float sfa[16][DD+1], sfb[16][DD+1];
    __shared__ float sb1[DD], sw2[2*DD];
    int tid = threadIdx.x;
    int i0 = blockIdx.y * 16, j0 = blockIdx.x * 16;
    for (int idx = tid; idx < 16*DD; idx += 256) {
        int r = idx >> 7, c = idx & 127;
        sfa[r][c] = (i0 + r < NN) ? g_fa[(i0+r)*DD + c] : 0.f;
        sfb[r][c] = (j0 + r < NN) ? g_fb[(j0+r)*DD + c] : 0.f;
    }
    if (tid < DD) sb1[tid] = b1v[tid];
    if (tid < 2*DD) sw2[tid] = W2[tid];
    __syncthreads();
    int ti = tid >> 4, tj = tid & 15;
    int i = i0 + ti, j = j0 + tj;
    if (i < NN && j < NN) {
        float a0 = b2v[0], a1 = b2v[1];
#pragma unroll 4
        for (int k = 0; k < DD; k++) {
            float v = fmaxf(sfa[ti][k] + sfb[tj][k] + sb1[k], 0.f);
            a0 += v * sw2[2*k];
            a1 += v * sw2[2*k+1];
        }
        int e = i*NN + j;
        float u0 = unoise[2*e], u1 = unoise[2*e+1];
        float g0 = -logf(-logf(u0 + 1e-10f) + 1e-10f);
        float g1 = -logf(-logf(u1 + 1e-10f) + 1e-10f);
        float m = ((a0 + g0) >= (a1 + g1)) ? 1.f : 0.f;
        if (i == j) m = 0.f;
        mask[e] = m;
    }
}

// ---------------- row-normalize mask -> A (padded layout, pre-rounded to tf32) ----------------
__global__ void rownorm_kernel(const float* __restrict__ mask) {
    int i = blockIdx.x;
    int tid = threadIdx.x;
    __shared__ float sred[256];
    float s = 0.f;
    for (int j = tid; j < NN; j += 256) s += mask[i*NN + j];
    sred[tid] = s;
    __syncthreads();
    for (int off = 128; off > 0; off >>= 1) {
        if (tid < off) sred[tid] += sred[tid+off];
        __syncthreads();
    }
    float inv = 1.f / (sred[0] + 1e-6f);
    for (int j = tid; j < NN; j += 256) {
        float v = mask[i*NN + j] * inv;
        uint32_t t;
        asm("cvt.rna.tf32.f32 %0, %1;" : "=r"(t) : "f"(v));
        g_A[i*KP + j] = __uint_as_float(t);
    }
}

// ---------------- set x column of g_cat ----------------
__global__ void set_x_kernel(const float* __restrict__ x, int bstride, int use_yprev) {
    int idx = blockIdx.x * blockDim.x + threadIdx.x;
    if (idx >= NN*BB) return;
    int n = idx >> 4, b = idx & 15;
    float v = use_yprev ? g_yprev[b*NN + n] : x[b*bstride + n];
    g_cat[n*NPS + b*INF] = v;
}

// ---------------- tf32 mma GEMM: C[MP,NPS] = A * X ----------------
// CTA tile 64x64, 128 threads (4 warps, 2x2), warp tile 32x32, mma.m16n8k8.tf32.
// grid (17,16)=272 -> 2 CTAs/SM. Double-buffered smem; B cvt'd to tf32 at fill.
#define APAD 36
#define BPAD 72
__global__ void __launch_bounds__(128) mma_gemm_kernel(int which) {
    const float* __restrict__ X = which ? g_cat2 : g_cat;
    float* __restrict__ C = which ? g_agg2 : g_agg;
    __shared__ __align__(16) float As[2][64][APAD];   // [m][k]
    __shared__ __align__(16) float Bs[2][32][BPAD];   // [k][n]

    int tid  = threadIdx.x;
    int lane = tid & 31;
    int wid  = tid >> 5;
    int wm = wid >> 1;                 // 0..1
    int wn = wid & 1;                  // 0..1
    int lr = lane >> 2;                // 0..7
    int lc = lane & 3;                 // 0..3
    int m0 = blockIdx.y * 64, n0 = blockIdx.x * 64;

    float acc[2][4][4];
#pragma unroll
    for (int mi = 0; mi < 2; mi++)
#pragma unroll
        for (int nj = 0; nj < 4; nj++)
#pragma unroll
            for (int q = 0; q < 4; q++) acc[mi][nj][q] = 0.f;

    float4 pa[4], pb[4];
    // preload k-tile 0 into regs
#pragma unroll
    for (int i = 0; i < 4; i++) {
        int q = tid + 128*i; int r = q >> 3, c = (q & 7) << 2;     // A: 64 rows x 8 float4
        pa[i] = *(const float4*)&g_A[(size_t)(m0 + r)*KP + c];
    }
#pragma unroll
    for (int i = 0; i < 4; i++) {
        int q = tid + 128*i; int r = q >> 4, c = (q & 15) << 2;    // B: 32 rows x 16 float4
        pb[i] = *(const float4*)&X[(size_t)r*NPS + n0 + c];
    }
    // store buffer 0 (B cvt'd to tf32 at fill)
#pragma unroll
    for (int i = 0; i < 4; i++) {
        int q = tid + 128*i; int r = q >> 3, c = (q & 7) << 2;
        *(float4*)&As[0][r][c] = pa[i];
    }
#pragma unroll
    for (int i = 0; i < 4; i++) {
        int q = tid + 128*i; int r = q >> 4, c = (q & 15) << 2;
        float4 v = pb[i];
        uint32_t t0, t1, t2, t3;
        asm("cvt.rna.tf32.f32 %0, %1;" : "=r"(t0) : "f"(v.x));
        asm("cvt.rna.tf32.f32 %0, %1;" : "=r"(t1) : "f"(v.y));
        asm("cvt.rna.tf32.f32 %0, %1;" : "=r"(t2) : "f"(v.z));
        asm("cvt.rna.tf32.f32 %0, %1;" : "=r"(t3) : "f"(v.w));
        *(float4*)&Bs[0][r][c] = make_float4(__uint_as_float(t0), __uint_as_float(t1),
                                             __uint_as_float(t2), __uint_as_float(t3));
    }
    __syncthreads();

    int buf = 0;
    for (int k0 = 32; k0 <= KP; k0 += 32) {
        if (k0 < KP) {
#pragma unroll
            for (int i = 0; i < 4; i++) {
                int q = tid + 128*i; int r = q >> 3, c = (q & 7) << 2;
                pa[i] = *(const float4*)&g_A[(size_t)(m0 + r)*KP + k0 + c];
            }
#pragma unroll
            for (int i = 0; i < 4; i++) {
                int q = tid + 128*i; int r = q >> 4, c = (q & 15) << 2;
                pb[i] = *(const float4*)&X[(size_t)(k0 + r)*NPS + n0 + c];
            }
        }
#pragma unroll
        for (int ks = 0; ks < 4; ks++) {
            int kb = ks * 8;
            uint32_t af[2][4];
#pragma unroll
            for (int mi = 0; mi < 2; mi++) {
                int rb = wm*32 + mi*16;
                af[mi][0] = __float_as_uint(As[buf][rb + lr][kb + lc]);
                af[mi][1] = __float_as_uint(As[buf][rb + 8 + lr][kb + lc]);
                af[mi][2] = __float_as_uint(As[buf][rb + lr][kb + 4 + lc]);
                af[mi][3] = __float_as_uint(As[buf][rb + 8 + lr][kb + 4 + lc]);
            }
            uint32_t bf[4][2];
#pragma unroll
            for (int nj = 0; nj < 4; nj++) {
                int nb = wn*32 + nj*8;
                bf[nj][0] = __float_as_uint(Bs[buf][kb + lc][nb + lr]);
                bf[nj][1] = __float_as_uint(Bs[buf][kb + 4 + lc][nb + lr]);
            }
#pragma unroll
            for (int mi = 0; mi < 2; mi++)
#pragma unroll
                for (int nj = 0; nj < 4; nj++) {
                    asm("mma.sync.aligned.m16n8k8.row.col.f32.tf32.tf32.f32 "
                        "{%0,%1,%2,%3}, {%4,%5,%6,%7}, {%8,%9}, {%0,%1,%2,%3};"
                        : "+f"(acc[mi][nj][0]), "+f"(acc[mi][nj][1]),
                          "+f"(acc[mi][nj][2]), "+f"(acc[mi][nj][3])
                        : "r"(af[mi][0]), "r"(af[mi][1]), "r"(af[mi][2]), "r"(af[mi][3]),
                          "r"(bf[nj][0]), "r"(bf[nj][1]));
                }
        }
        if (k0 < KP) {
            int nb2 = buf ^ 1;
#pragma unroll
            for (int i = 0; i < 4; i++) {
                int q = tid + 128*i; int r = q >> 3, c = (q & 7) << 2;
                *(float4*)&As[nb2][r][c] = pa[i];
            }
#pragma unroll
            for (int i = 0; i < 4; i++) {
                int q = tid + 128*i; int r = q >> 4, c = (q & 15) << 2;
                float4 v = pb[i];
                uint32_t t0, t1, t2, t3;
                asm("cvt.rna.tf32.f32 %0, %1;" : "=r"(t0) : "f"(v.x));
                asm("cvt.rna.tf32.f32 %0, %1;" : "=r"(t1) : "f"(v.y));
                asm("cvt.rna.tf32.f32 %0, %1;" : "=r"(t2) : "f"(v.z));
                asm("cvt.rna.tf32.f32 %0, %1;" : "=r"(t3) : "f"(v.w));
                *(float4*)&Bs[nb2][r][c] = make_float4(__uint_as_float(t0), __uint_as_float(t1),
                                                       __uint_as_float(t2), __uint_as_float(t3));
            }
            __syncthreads();
            buf = nb2;
        }
    }

    // epilogue
#pragma unroll
    for (int mi = 0; mi < 2; mi++)
#pragma unroll
        for (int nj = 0; nj < 4; nj++) {
            int r1 = m0 + wm*32 + mi*16 + lr;
            int col = n0 + wn*32 + nj*8 + lc*2;
            *(float2*)&C[(size_t)r1*NPS + col] = make_float2(acc[mi][nj][0], acc[mi][nj][1]);
            *(float2*)&C[(size_t)(r1 + 8)*NPS + col] = make_float2(acc[mi][nj][2], acc[mi][nj][3]);
        }
}

// ---------------- gates: ru = sigmoid(cat@W0 + agg@W1 + bru); build cat2; store u ----------------
#define GATES_SMEM ((INF*DD*2 + 64*66*2) * 4)
__global__ void gates_kernel(const float* __restrict__ Wru0, const float* __restrict__ Wru1,
                             const float* __restrict__ bru) {
    extern __shared__ __align__(16) float sm[];
    float* sW0  = sm;                    // 65*128
    float* sW1  = sW0 + INF*DD;          // 65*128
    float* srow = sW1 + INF*DD;          // 64*66 (cat)
    float* sag  = srow + 64*66;          // 64*66 (agg)
    int tid = threadIdx.x;
    int r0 = blockIdx.x * 64;
    for (int i = tid; i < INF*DD; i += 512) { sW0[i] = Wru0[i]; sW1[i] = Wru1[i]; }
    for (int i = tid; i < 64*INF; i += 512) {
        int lr = i / INF, f = i % INF;
        int rid = r0 + lr, n = rid >> 4, b = rid & 15;
        srow[lr*66 + f] = g_cat[n*NPS + b*INF + f];
        sag [lr*66 + f] = g_agg[n*NPS + b*INF + f];
    }
    __syncthreads();
    int rt = tid >> 5;
    int ct = tid & 31;
    float acc[4][4];
#pragma unroll
    for (int i = 0; i < 4; i++)
#pragma unroll
        for (int j = 0; j < 4; j++) acc[i][j] = bru[ct*4 + j];
    for (int f = 0; f < INF; f++) {
        float a[4], g[4];
#pragma unroll
        for (int i = 0; i < 4; i++) {
            a[i] = srow[(rt*4+i)*66 + f];
            g[i] = sag [(rt*4+i)*66 + f];
        }
        float4 w0 = *(const float4*)&sW0[f*DD + ct*4];
        float4 w1 = *(const float4*)&sW1[f*DD + ct*4];
#pragma unroll
        for (int i = 0; i < 4; i++) {
            acc[i][0] += a[i]*w0.x + g[i]*w1.x;
            acc[i][1] += a[i]*w0.y + g[i]*w1.y;
            acc[i][2] += a[i]*w0.z + g[i]*w1.z;
            acc[i][3] += a[i]*w0.w + g[i]*w1.w;
        }
    }
#pragma unroll
    for (int i = 0; i < 4; i++) {
        int lr = rt*4 + i, rid = r0 + lr, n = rid >> 4, b = rid & 15;
#pragma unroll
        for (int j = 0; j < 4; j++) {
            int c = ct*4 + j;
            float s = 1.f / (1.f + expf(-acc[i][j]));
            if (c < HID) {
                float hv = srow[lr*66 + 1 + c];
                g_cat2[n*NPS + b*INF + 1 + c] = s * hv;
            } else {
                g_u[rid*HID + (c - HID)] = s;
            }
        }
    }
    if (tid < 64) {
        int rid = r0 + tid, n = rid >> 4, b = rid & 15;
        g_cat2[n*NPS + b*INF] = srow[tid*66];    // x column
    }
}

// ---------------- update: c = tanh(cat2@Wc0 + agg2@Wc1 + bc); h = u*h + (1-u)*c ----------------
#define UPD_SMEM ((INF*HID*2 + 64*66*2) * 4)
__global__ void update_kernel(const float* __restrict__ Wc0, const float* __restrict__ Wc1,
                              const float* __restrict__ bc) {
    extern __shared__ __align__(16) float sm[];
    float* sW0  = sm;                     // 65*64
    float* sW1  = sW0 + INF*HID;
    float* srow = sW1 + INF*HID;          // 64*66
    float* sag  = srow + 64*66;
    int tid = threadIdx.x;
    int r0 = blockIdx.x * 64;
    for (int i = tid; i < INF*HID; i += 256) { sW0[i] = Wc0[i]; sW1[i] = Wc1[i]; }
    for (int i = tid; i < 64*INF; i += 256) {
        int lr = i / INF, f = i % INF;
        int rid = r0 + lr, n = rid >> 4, b = rid & 15;
        srow[lr*66 + f] = g_cat2[n*NPS + b*INF + f];
        sag [lr*66 + f] = g_agg2[n*NPS + b*INF + f];
    }
    __syncthreads();
    int rt = tid >> 4;
    int ct = tid & 15;
    float acc[4][4];
#pragma unroll
    for (int i = 0; i < 4; i++)
#pragma unroll
        for (int j = 0; j < 4; j++) acc[i][j] = bc[ct*4 + j];
    for (int f = 0; f < INF; f++) {
        float a[4], g[4];
#pragma unroll
        for (int i = 0; i < 4; i++) {
            a[i] = srow[(rt*4+i)*66 + f];
            g[i] = sag [(rt*4+i)*66 + f];
        }
        float4 w0 = *(const float4*)&sW0[f*HID + ct*4];
        float4 w1 = *(const float4*)&sW1[f*HID + ct*4];
#pragma unroll
        for (int i = 0; i < 4; i++) {
            acc[i][0] += a[i]*w0.x + g[i]*w1.x;
            acc[i][1] += a[i]*w0.y + g[i]*w1.y;
            acc[i][2] += a[i]*w0.z + g[i]*w1.z;
            acc[i][3] += a[i]*w0.w + g[i]*w1.w;
        }
    }
#pragma unroll
    for (int i = 0; i < 4; i++) {
        int lr = rt*4 + i, rid = r0 + lr, n = rid >> 4, b = rid & 15;
#pragma unroll
        for (int j = 0; j < 4; j++) {
            int c = ct*4 + j;
            float cv = tanhf(acc[i][j]);
            float u = g_u[rid*HID + c];
            float hv = g_h[rid*HID + c];
            float hn = u*hv + (1.f - u)*cv;
            g_h[rid*HID + c] = hn;
            g_cat[n*NPS + b*INF + 1 + c] = hn;   // feed next step's cat directly
        }
    }
}

// ---------------- projection (decoder): y = h@proj_w + proj_b ----------------
__global__ void proj_kernel(const float* __restrict__ pw, const float* __restrict__ pb,
                            float* __restrict__ outp, int t) {
    int gw = (blockIdx.x * blockDim.x + threadIdx.x) >> 5;
    int lane = threadIdx.x & 31;
    if (gw >= BB*NN) return;
    int rid = gw;                        // rid = n*16+b
    float s = g_h[rid*HID + lane]*pw[lane] + g_h[rid*HID + 32 + lane]*pw[32 + lane];
#pragma unroll
    for (int off = 16; off > 0; off >>= 1) s += __shfl_down_sync(0xffffffffu, s, off);
    if (lane == 0) {
        int n = rid >> 4, b = rid & 15;
        float y = s + pb[0];
        g_yprev[b*NN + n] = y;
        outp[(b*HH + t)*NN + n] = y;
    }
}

// ---------------- loss: mean((outputs-targets)^2), single block deterministic ----------------
__global__ void loss_kernel(const float* __restrict__ outp, const float* __restrict__ targ,
                            float* __restrict__ lossout) {
    __shared__ double sred[256];
    int tid = threadIdx.x;
    double s = 0.0;
    for (int i = tid; i < BB*HH*NN; i += 256) {
        float d = outp[i] - targ[i];
        s += (double)d * (double)d;
    }
    sred[tid] = s;
    __syncthreads();
    for (int off = 128; off > 0; off >>= 1) {
        if (tid < off) sred[tid] += sred[tid+off];
        __syncthreads();
    }
    if (tid == 0) lossout[0] = (float)(sred[0] / (double)(BB*HH*NN));
}

// ---------------- host ----------------
extern "C" void kernel_launch(void* const* d_in, const int* in_sizes, int n_in,
                              void* d_out, int out_size) {
    const float* inputs  = (const float*)d_in[0];
    const float* entire  = (const float*)d_in[1];
    const float* targets = (const float*)d_in[2];
    const float* unoise  = (const float*)d_in[3];
    const float* c1w = (const float*)d_in[4];
    const float* c1b = (const float*)d_in[5];
    const float* c2w = (const float*)d_in[6];
    const float* c2b = (const float*)d_in[7];
    const float* fcw = (const float*)d_in[8];
    const float* fcb = (const float*)d_in[9];
    const float* Wa  = (const float*)d_in[10];
    const float* Wb  = (const float*)d_in[11];
    const float* b1  = (const float*)d_in[12];
    const float* W2  = (const float*)d_in[13];
    const float* b2  = (const float*)d_in[14];
    const float* eWru0 = (const float*)d_in[15];
    const float* eWru1 = (const float*)d_in[16];
    const float* ebru  = (const float*)d_in[17];
    const float* eWc0  = (const float*)d_in[18];
    const float* eWc1  = (const float*)d_in[19];
    const float* ebc   = (const float*)d_in[20];
    const float* dWru0 = (const float*)d_in[21];
    const float* dWru1 = (const float*)d_in[22];
    const float* dbru  = (const float*)d_in[23];
    const float* dWc0  = (const float*)d_in[24];
    const float* dWc1  = (const float*)d_in[25];
    const float* dbc   = (const float*)d_in[26];
    const float* pw    = (const float*)d_in[27];
    const float* pb    = (const float*)d_in[28];

    float* out      = (float*)d_out;
    float* maskout  = out;                       // N*N
    float* outputs  = out + NN*NN;               // B*H*N
    float* lossout  = out + NN*NN + BB*HH*NN;    // 1

    cudaFuncSetAttribute(gates_kernel,  cudaFuncAttributeMaxDynamicSharedMemorySize, GATES_SMEM);
    cudaFuncSetAttribute(update_kernel, cudaFuncAttributeMaxDynamicSharedMemorySize, UPD_SMEM);

    init_kernel<<<(KP*NPS + 255)/256, 256>>>();
    conv_pool_kernel<<<NN, 256>>>(entire, c1w, c1b, c2w, c2b);
    fc_fab_kernel<<<NN, DD>>>(fcw, fcb, Wa, Wb);
    dim3 eg(63, 63);
    edge_kernel<<<eg, 256>>>(b1, W2, b2, unoise, maskout);
    rownorm_kernel<<<NN, 256>>>(maskout);

    dim3 gg(NPS/64, MP/64);   // (17, 16) = 272 blocks, 2 CTAs/SM
    int sx_blocks = (NN*BB + 255)/256;

    // encoder
    for (int s = 0; s < SS; s++) {
        set_x_kernel<<<sx_blocks, 256>>>(inputs + s*NN, SS*NN, 0);
        mma_gemm_kernel<<<gg, 128>>>(0);
        gates_kernel<<<BB*NN/64, 512, GATES_SMEM>>>(eWru0, eWru1, ebru);
        mma_gemm_kernel<<<gg, 128>>>(1);
        update_kernel<<<BB*NN/64, 256, UPD_SMEM>>>(eWc0, eWc1, ebc);
    }
    // decoder
    for (int t = 0; t < HH; t++) {
        set_x_kernel<<<sx_blocks, 256>>>(inputs, NN, 1);   // x from g_yprev
        mma_gemm_kernel<<<gg, 128>>>(0);
        gates_kernel<<<BB*NN/64, 512, GATES_SMEM>>>(dWru0, dWru1, dbru);
        mma_gemm_kernel<<<gg, 128>>>(1);
        update_kernel<<<BB*NN/64, 256, UPD_SMEM>>>(dWc0, dWc1, dbc);
        proj_kernel<<<(BB*NN*32 + 255)/256, 256>>>(pw, pb, outputs, t);
    }
    loss_kernel<<<1, 256>>>(outputs, targets, lossout);
}